// round 2
// baseline (speedup 1.0000x reference)
#include <cuda_runtime.h>

// Problem constants
#define Cdim 1024
#define Hn   16
#define DHn  64
#define NB   8
#define Lseq 4096
#define Mrows (NB * Lseq)      // 32768
#define ATT_SCALE 0.125f       // 1/sqrt(64)

// ---------------------------------------------------------------------------
// Scratch (device globals; no allocations allowed)
// ---------------------------------------------------------------------------
__device__ float g_Q[(size_t)Mrows * Cdim];   // queries (kept until T epilogue)
__device__ float g_K[(size_t)Mrows * Cdim];   // keys, reused as T
__device__ float g_V[(size_t)Mrows * Cdim];   // scaled values
__device__ float g_logits[(size_t)Mrows * Hn];
__device__ float g_wbuf[(size_t)NB * Hn * Lseq];
__device__ float g_pq[NB * Cdim];
__device__ float g_pk[NB * Cdim];

// ---------------------------------------------------------------------------
// SGEMM: C[M,1024] = A[M,1024] @ W[1024,1024] + bias, optional epilogues:
//   colscale != null :  *= colscale[n*C + col]   (n = row >> 12)
//   addmat   != null :  += addmat[row, col]
// BM=BN=128, BK=8, 256 threads, 8x8 per thread.
// ---------------------------------------------------------------------------
__global__ __launch_bounds__(256) void sgemm_kernel(
    const float* __restrict__ A, const float* __restrict__ W,
    const float* __restrict__ bias, float* __restrict__ Cc,
    const float* __restrict__ colscale, const float* __restrict__ addmat)
{
    const int K = Cdim, Nn = Cdim;
    __shared__ float As[8][128];
    __shared__ float Bs[8][128];

    int tid  = threadIdx.x;
    int brow = blockIdx.y * 128;
    int bcol = blockIdx.x * 128;

    int arow = tid >> 1;           // 0..127
    int acol = (tid & 1) << 2;     // 0 or 4
    int bkr  = tid >> 5;           // 0..7
    int bcl  = (tid & 31) << 2;    // 0..124
    int trow = (tid >> 4) << 3;    // 0..120
    int tcol = (tid & 15) << 3;    // 0..120

    float acc[8][8];
#pragma unroll
    for (int i = 0; i < 8; i++)
#pragma unroll
        for (int j = 0; j < 8; j++) acc[i][j] = 0.f;

    const float* Ab = A + (size_t)(brow + arow) * K + acol;
    const float* Wb = W + (size_t)bkr * Nn + bcol + bcl;

    for (int k0 = 0; k0 < K; k0 += 8) {
        float4 av = *(const float4*)(Ab + k0);
        As[acol + 0][arow] = av.x;
        As[acol + 1][arow] = av.y;
        As[acol + 2][arow] = av.z;
        As[acol + 3][arow] = av.w;
        float4 bv = *(const float4*)(Wb + (size_t)k0 * Nn);
        *(float4*)&Bs[bkr][bcl] = bv;
        __syncthreads();

#pragma unroll
        for (int k = 0; k < 8; k++) {
            float4 a0 = *(const float4*)&As[k][trow];
            float4 a1 = *(const float4*)&As[k][trow + 4];
            float4 b0 = *(const float4*)&Bs[k][tcol];
            float4 b1 = *(const float4*)&Bs[k][tcol + 4];
            float af[8] = {a0.x, a0.y, a0.z, a0.w, a1.x, a1.y, a1.z, a1.w};
            float bf[8] = {b0.x, b0.y, b0.z, b0.w, b1.x, b1.y, b1.z, b1.w};
#pragma unroll
            for (int i = 0; i < 8; i++)
#pragma unroll
                for (int j = 0; j < 8; j++)
                    acc[i][j] = fmaf(af[i], bf[j], acc[i][j]);
        }
        __syncthreads();
    }

    int row0 = brow + trow;
    int col0 = bcol + tcol;
    int nidx = row0 >> 12;     // 4096 rows per batch; BM=128 never straddles n

    float bvals[8], svals[8];
#pragma unroll
    for (int j = 0; j < 8; j++) bvals[j] = bias[col0 + j];
    if (colscale) {
#pragma unroll
        for (int j = 0; j < 8; j++) svals[j] = colscale[nidx * Cdim + col0 + j];
    }

#pragma unroll
    for (int i = 0; i < 8; i++) {
        size_t rowoff = (size_t)(row0 + i) * Nn + col0;
#pragma unroll
        for (int j = 0; j < 8; j += 4) {
            float4 v;
            v.x = acc[i][j + 0] + bvals[j + 0];
            v.y = acc[i][j + 1] + bvals[j + 1];
            v.z = acc[i][j + 2] + bvals[j + 2];
            v.w = acc[i][j + 3] + bvals[j + 3];
            if (colscale) {
                v.x *= svals[j + 0]; v.y *= svals[j + 1];
                v.z *= svals[j + 2]; v.w *= svals[j + 3];
            }
            if (addmat) {
                float4 ad = *(const float4*)(addmat + rowoff + j);
                v.x += ad.x; v.y += ad.y; v.z += ad.z; v.w += ad.w;
            }
            *(float4*)(Cc + rowoff + j) = v;
        }
    }
}

// ---------------------------------------------------------------------------
// logits[row, h] = (sum_c A[row,c] * (sv? sv[n,c]:1) * W16[c,h] + b16[h]) * SCALE
// One warp per row, 8 rows per block.
// ---------------------------------------------------------------------------
__global__ __launch_bounds__(256) void attn_logits_kernel(
    const float* __restrict__ A, const float* __restrict__ W16,
    const float* __restrict__ b16, const float* __restrict__ scalevec,
    float* __restrict__ logits)
{
    int warp = threadIdx.x >> 5, lane = threadIdx.x & 31;
    int row = blockIdx.x * 8 + warp;
    int n = row >> 12;
    const float* arow = A + (size_t)row * Cdim;
    const float* sv = scalevec ? scalevec + (size_t)n * Cdim : nullptr;

    float acc[16];
#pragma unroll
    for (int h = 0; h < 16; h++) acc[h] = 0.f;

    for (int c = lane; c < Cdim; c += 32) {
        float a = arow[c];
        if (sv) a *= sv[c];
        const float4* w4 = (const float4*)(W16 + (size_t)c * 16);
        float4 w0 = w4[0], w1 = w4[1], w2 = w4[2], w3 = w4[3];
        acc[0]  = fmaf(a, w0.x, acc[0]);  acc[1]  = fmaf(a, w0.y, acc[1]);
        acc[2]  = fmaf(a, w0.z, acc[2]);  acc[3]  = fmaf(a, w0.w, acc[3]);
        acc[4]  = fmaf(a, w1.x, acc[4]);  acc[5]  = fmaf(a, w1.y, acc[5]);
        acc[6]  = fmaf(a, w1.z, acc[6]);  acc[7]  = fmaf(a, w1.w, acc[7]);
        acc[8]  = fmaf(a, w2.x, acc[8]);  acc[9]  = fmaf(a, w2.y, acc[9]);
        acc[10] = fmaf(a, w2.z, acc[10]); acc[11] = fmaf(a, w2.w, acc[11]);
        acc[12] = fmaf(a, w3.x, acc[12]); acc[13] = fmaf(a, w3.y, acc[13]);
        acc[14] = fmaf(a, w3.z, acc[14]); acc[15] = fmaf(a, w3.w, acc[15]);
    }
#pragma unroll
    for (int h = 0; h < 16; h++) {
        float v = acc[h];
#pragma unroll
        for (int o = 16; o; o >>= 1) v += __shfl_xor_sync(0xffffffffu, v, o);
        if (lane == h) logits[(size_t)row * 16 + h] = (v + b16[h]) * ATT_SCALE;
    }
}

// ---------------------------------------------------------------------------
// softmax over L (per n,h). logits layout [n*L, H]; output [n, h, L].
// One block per (n,h).
// ---------------------------------------------------------------------------
__global__ __launch_bounds__(256) void softmax_L_kernel(
    const float* __restrict__ logits, float* __restrict__ w_out)
{
    int n = blockIdx.x / Hn, h = blockIdx.x % Hn;
    __shared__ float buf[Lseq];
    __shared__ float red[256];
    int tid = threadIdx.x;

    float m = -1e30f;
    for (int l = tid; l < Lseq; l += 256) {
        float v = logits[((size_t)n * Lseq + l) * Hn + h];
        buf[l] = v;
        m = fmaxf(m, v);
    }
    red[tid] = m; __syncthreads();
    for (int s = 128; s; s >>= 1) {
        if (tid < s) red[tid] = fmaxf(red[tid], red[tid + s]);
        __syncthreads();
    }
    m = red[0]; __syncthreads();

    float sum = 0.f;
    for (int l = tid; l < Lseq; l += 256) {
        float e = __expf(buf[l] - m);
        buf[l] = e;
        sum += e;
    }
    red[tid] = sum; __syncthreads();
    for (int s = 128; s; s >>= 1) {
        if (tid < s) red[tid] += red[tid + s];
        __syncthreads();
    }
    float inv = 1.f / red[0];

    float* wp = w_out + ((size_t)n * Hn + h) * Lseq;
    for (int l = tid; l < Lseq; l += 256) wp[l] = buf[l] * inv;
}

// ---------------------------------------------------------------------------
// pooled[n, h*64+dh] = sum_l w[n,h,l] * A[n,l, h*64+dh]
// Block (1024 threads) per (h, n); 16 L-segments of 256.
// ---------------------------------------------------------------------------
__global__ __launch_bounds__(1024) void pool_kernel(
    const float* __restrict__ w, const float* __restrict__ A,
    float* __restrict__ pooled)
{
    int h = blockIdx.x, n = blockIdx.y;
    int tid = threadIdx.x;
    int dh = tid & 63, g = tid >> 6;   // 16 segments

    const float* wp = w + ((size_t)n * Hn + h) * Lseq + g * 256;
    const float* ap = A + ((size_t)(n * Lseq + g * 256)) * Cdim + h * 64 + dh;

    float a0 = 0.f, a1 = 0.f, a2 = 0.f, a3 = 0.f;
    for (int l = 0; l < 256; l += 4) {
        a0 = fmaf(wp[l + 0], ap[(size_t)(l + 0) * Cdim], a0);
        a1 = fmaf(wp[l + 1], ap[(size_t)(l + 1) * Cdim], a1);
        a2 = fmaf(wp[l + 2], ap[(size_t)(l + 2) * Cdim], a2);
        a3 = fmaf(wp[l + 3], ap[(size_t)(l + 3) * Cdim], a3);
    }
    __shared__ float red[1024];
    red[tid] = a0 + a1 + a2 + a3;
    __syncthreads();
    if (tid < 64) {
        float s = 0.f;
#pragma unroll
        for (int gg = 0; gg < 16; gg++) s += red[dh + gg * 64];
        pooled[(size_t)n * Cdim + h * 64 + dh] = s;
    }
}

// ---------------------------------------------------------------------------
// Launch. Inputs (metadata order):
// 0 x_q, 1 x_kv, 2 Wq, 3 bq, 4 Wqa, 5 bqa, 6 Wk, 7 bk, 8 Wka, 9 bka,
// 10 Wv, 11 bv, 12 Wt, 13 bt, 14 Wp, 15 bp
// ---------------------------------------------------------------------------
extern "C" void kernel_launch(void* const* d_in, const int* in_sizes, int n_in,
                              void* d_out, int out_size)
{
    const float* x_q  = (const float*)d_in[0];
    const float* x_kv = (const float*)d_in[1];
    const float* Wq   = (const float*)d_in[2];
    const float* bq   = (const float*)d_in[3];
    const float* Wqa  = (const float*)d_in[4];
    const float* bqa  = (const float*)d_in[5];
    const float* Wk   = (const float*)d_in[6];
    const float* bk   = (const float*)d_in[7];
    const float* Wka  = (const float*)d_in[8];
    const float* bka  = (const float*)d_in[9];
    const float* Wv   = (const float*)d_in[10];
    const float* bv   = (const float*)d_in[11];
    const float* Wt   = (const float*)d_in[12];
    const float* bt   = (const float*)d_in[13];
    const float* Wp   = (const float*)d_in[14];
    const float* bp   = (const float*)d_in[15];
    float* out = (float*)d_out;

    float *Qb, *Kb, *Vb, *lg, *wb, *pq, *pk;
    cudaGetSymbolAddress((void**)&Qb, g_Q);
    cudaGetSymbolAddress((void**)&Kb, g_K);
    cudaGetSymbolAddress((void**)&Vb, g_V);
    cudaGetSymbolAddress((void**)&lg, g_logits);
    cudaGetSymbolAddress((void**)&wb, g_wbuf);
    cudaGetSymbolAddress((void**)&pq, g_pq);
    cudaGetSymbolAddress((void**)&pk, g_pk);

    dim3 ggrid(Cdim / 128, Mrows / 128);   // 8 x 256

    // 1. Q = x_q @ Wq + bq
    sgemm_kernel<<<ggrid, 256>>>(x_q, Wq, bq, Qb, nullptr, nullptr);
    // 2. q attention weights + pool
    attn_logits_kernel<<<Mrows / 8, 256>>>(Qb, Wqa, bqa, nullptr, lg);
    softmax_L_kernel<<<NB * Hn, 256>>>(lg, wb);
    pool_kernel<<<dim3(Hn, NB), 1024>>>(wb, Qb, pq);
    // 3. K = x_kv @ Wk + bk
    sgemm_kernel<<<ggrid, 256>>>(x_kv, Wk, bk, Kb, nullptr, nullptr);
    // 4. k attention weights (gated by pooled_q) + pool (on UNSCALED keys)
    attn_logits_kernel<<<Mrows / 8, 256>>>(Kb, Wka, bka, pq, lg);
    softmax_L_kernel<<<NB * Hn, 256>>>(lg, wb);
    pool_kernel<<<dim3(Hn, NB), 1024>>>(wb, Kb, pk);
    // 5. Vs = (x_kv @ Wv + bv) * pooled_k[n, col]
    sgemm_kernel<<<ggrid, 256>>>(x_kv, Wv, bv, Vb, pk, nullptr);
    // 6. T = Vs @ Wt + bt + Q   (reuse Kb as T buffer)
    sgemm_kernel<<<ggrid, 256>>>(Vb, Wt, bt, Kb, nullptr, Qb);
    // 7. out = T @ Wp + bp
    sgemm_kernel<<<ggrid, 256>>>(Kb, Wp, bp, out, nullptr, nullptr);
}

// round 4
// speedup vs baseline: 4.4011x; 4.4011x over previous
#include <cuda_runtime.h>
#include <cuda_bf16.h>
#include <cstdint>

#define Cdim 1024
#define Hn   16
#define NB   8
#define Lseq 4096
#define Mrows (NB * Lseq)      // 32768
#define ATT_SCALE 0.125f

// ---------------------------------------------------------------------------
// Scratch
// ---------------------------------------------------------------------------
__device__ float g_Q[(size_t)Mrows * Cdim];
__device__ float g_K[(size_t)Mrows * Cdim];
__device__ float g_logits[(size_t)Mrows * Hn];
__device__ float g_wbuf[(size_t)NB * Hn * Lseq];
__device__ float g_pq[NB * Cdim];
__device__ float g_pk[NB * Cdim];

__device__ __nv_bfloat16 g_xq_hi[(size_t)Mrows * Cdim];
__device__ __nv_bfloat16 g_xq_lo[(size_t)Mrows * Cdim];
__device__ __nv_bfloat16 g_xkv_hi[(size_t)Mrows * Cdim];
__device__ __nv_bfloat16 g_xkv_lo[(size_t)Mrows * Cdim];
__device__ __nv_bfloat16 g_V_hi[(size_t)Mrows * Cdim];
__device__ __nv_bfloat16 g_V_lo[(size_t)Mrows * Cdim];
__device__ __nv_bfloat16 g_T_hi[(size_t)Mrows * Cdim];
__device__ __nv_bfloat16 g_T_lo[(size_t)Mrows * Cdim];
// transposed (K-major, [n][k]) weights, 5 matrices
__device__ __nv_bfloat16 g_WT_hi[5][(size_t)Cdim * Cdim];
__device__ __nv_bfloat16 g_WT_lo[5][(size_t)Cdim * Cdim];

// ---------------------------------------------------------------------------
// PTX helpers (family-safe: cp.async / ldmatrix / mma.sync only)
// ---------------------------------------------------------------------------
__device__ __forceinline__ uint32_t smem_u32(const void* p) {
    uint32_t a;
    asm("{ .reg .u64 t; cvta.to.shared.u64 t, %1; cvt.u32.u64 %0, t; }" : "=r"(a) : "l"(p));
    return a;
}
__device__ __forceinline__ void cpa16(uint32_t dst, const void* src) {
    asm volatile("cp.async.cg.shared.global [%0], [%1], 16;" :: "r"(dst), "l"(src) : "memory");
}
__device__ __forceinline__ void cpa_commit() {
    asm volatile("cp.async.commit_group;" ::: "memory");
}
__device__ __forceinline__ void cpa_wait2() {
    asm volatile("cp.async.wait_group 2;" ::: "memory");
}
__device__ __forceinline__ void ldm_x4(uint32_t* r, uint32_t addr) {
    asm volatile("ldmatrix.sync.aligned.m8n8.x4.shared.b16 {%0,%1,%2,%3}, [%4];"
                 : "=r"(r[0]), "=r"(r[1]), "=r"(r[2]), "=r"(r[3]) : "r"(addr));
}
__device__ __forceinline__ void mma_bf16(float* c, const uint32_t* a, const uint32_t* b) {
    asm volatile(
        "mma.sync.aligned.m16n8k16.row.col.f32.bf16.bf16.f32 "
        "{%0,%1,%2,%3}, {%4,%5,%6,%7}, {%8,%9}, {%0,%1,%2,%3};"
        : "+f"(c[0]), "+f"(c[1]), "+f"(c[2]), "+f"(c[3])
        : "r"(a[0]), "r"(a[1]), "r"(a[2]), "r"(a[3]), "r"(b[0]), "r"(b[1]));
}

// ---------------------------------------------------------------------------
// HMMA GEMM: out[M=32768, N=1024] = A[M,1024] @ W[1024,N] (+epilogues)
// A bf16 hi/lo row-major; W bf16 hi/lo K-major (WT[n][k]).
// Block 128x128, BK=32, 4-stage cp.async, 8 warps of 64x32.
// 3-term split: Ahi*Whi + Alo*Whi + Ahi*Wlo.
// ---------------------------------------------------------------------------
#define ROWB   80                  // padded smem row stride (bytes) per 32 bf16
#define TILEB  (128 * ROWB)        // 10240 per operand tile
#define STAGEB (4 * TILEB)         // Ahi, Alo, Bhi, Blo
#define STAGES 4
#define SMEMB  (STAGES * STAGEB)   // 163840

__device__ __forceinline__ void issue_stage(
    uint32_t sb, int s, int chunk, int tid,
    const __nv_bfloat16* Ahi, const __nv_bfloat16* Alo,
    const __nv_bfloat16* Bhi, const __nv_bfloat16* Blo,
    int grow0, int ncol0)
{
    uint32_t stb = sb + (uint32_t)s * STAGEB;
    int k0 = chunk * 32;
#pragma unroll
    for (int j = 0; j < 8; j++) {
        int id = tid + j * 256;           // 0..2047
        int t4 = id >> 9;                 // operand tile
        int w  = id & 511;
        int r  = w >> 2, c = w & 3;       // row, 16B chunk
        const __nv_bfloat16* src = (t4 == 0) ? Ahi : (t4 == 1) ? Alo
                                  : (t4 == 2) ? Bhi : Blo;
        int rb = (t4 < 2) ? grow0 : ncol0;
        const void* g = src + ((size_t)(rb + r) * Cdim + k0 + c * 8);
        cpa16(stb + (uint32_t)t4 * TILEB + (uint32_t)(r * ROWB + c * 16), g);
    }
}

__global__ void __launch_bounds__(256, 1) mma_gemm(
    const __nv_bfloat16* __restrict__ Ahi, const __nv_bfloat16* __restrict__ Alo,
    const __nv_bfloat16* __restrict__ Bhi, const __nv_bfloat16* __restrict__ Blo,
    const float* __restrict__ bias, const float* __restrict__ colscale,
    const float* __restrict__ addmat,
    float* __restrict__ outf,
    __nv_bfloat16* __restrict__ out_hi, __nv_bfloat16* __restrict__ out_lo)
{
    extern __shared__ char smem[];
    uint32_t sb = smem_u32(smem);
    int tid = threadIdx.x;
    int lane = tid & 31, wid = tid >> 5;
    int wm = wid & 1, wc = wid >> 1;           // warp 64x32 tile: 2 x 4 grid
    int bM = blockIdx.y * 128, bN = blockIdx.x * 128;

    float acc[4][4][4];
#pragma unroll
    for (int i = 0; i < 4; i++)
#pragma unroll
        for (int j = 0; j < 4; j++)
#pragma unroll
            for (int q = 0; q < 4; q++) acc[i][j][q] = 0.f;

    // precomputed ldmatrix lane offsets
    int grp = lane >> 3, l7 = lane & 7;
    // A: row = m0 + l7 + ((grp&1)<<3), kbyte = kk*2 + ((grp>>1)<<4)
    uint32_t a_off = (uint32_t)((l7 + ((grp & 1) << 3)) * ROWB + ((grp >> 1) << 4));
    // B: row = n0 + l7 + ((grp>>1)<<3), kbyte = kk*2 + ((grp&1)<<4)
    uint32_t b_off = (uint32_t)((l7 + ((grp >> 1) << 3)) * ROWB + ((grp & 1) << 4));

    // prologue
#pragma unroll
    for (int s = 0; s < 3; s++) {
        issue_stage(sb, s, s, tid, Ahi, Alo, Bhi, Blo, bM, bN);
        cpa_commit();
    }

    for (int k = 0; k < 32; k++) {
        cpa_wait2();
        __syncthreads();
        if (k + 3 < 32)
            issue_stage(sb, (k + 3) & 3, k + 3, tid, Ahi, Alo, Bhi, Blo, bM, bN);
        cpa_commit();

        uint32_t st = sb + (uint32_t)(k & 3) * STAGEB;
#pragma unroll
        for (int kk = 0; kk < 2; kk++) {
            uint32_t kb = (uint32_t)(kk * 32);   // kk*16 elems * 2B
            // B fragments: 2 halves of 16 n-rows each
            uint32_t bh[8], bl[8];
#pragma unroll
            for (int h = 0; h < 2; h++) {
                uint32_t nrow = (uint32_t)((wc * 32 + h * 16) * ROWB);
                ldm_x4(bh + h * 4, st + 2 * TILEB + nrow + b_off + kb);
                ldm_x4(bl + h * 4, st + 3 * TILEB + nrow + b_off + kb);
            }
#pragma unroll
            for (int mt = 0; mt < 4; mt++) {
                uint32_t mrow = (uint32_t)((wm * 64 + mt * 16) * ROWB);
                uint32_t ah[4], al[4];
                ldm_x4(ah, st + 0 * TILEB + mrow + a_off + kb);
                ldm_x4(al, st + 1 * TILEB + mrow + a_off + kb);
#pragma unroll
                for (int nt = 0; nt < 4; nt++) {
                    mma_bf16(acc[mt][nt], ah, &bh[nt * 2]);
                    mma_bf16(acc[mt][nt], al, &bh[nt * 2]);
                    mma_bf16(acc[mt][nt], ah, &bl[nt * 2]);
                }
            }
        }
    }

    // ---------------- epilogue ----------------
    int nidx = bM >> 12;   // batch index (128-row tiles never straddle)
#pragma unroll
    for (int mt = 0; mt < 4; mt++) {
        int m0 = bM + wm * 64 + mt * 16 + (lane >> 2);
#pragma unroll
        for (int nt = 0; nt < 4; nt++) {
            int n = bN + wc * 32 + nt * 8 + (lane & 3) * 2;
            float b0 = bias[n], b1 = bias[n + 1];
            float v0 = acc[mt][nt][0] + b0, v1 = acc[mt][nt][1] + b1;
            float v2 = acc[mt][nt][2] + b0, v3 = acc[mt][nt][3] + b1;
            if (colscale) {
                float s0 = colscale[nidx * Cdim + n];
                float s1 = colscale[nidx * Cdim + n + 1];
                v0 *= s0; v1 *= s1; v2 *= s0; v3 *= s1;
            }
            size_t o0 = (size_t)m0 * Cdim + n;
            size_t o1 = (size_t)(m0 + 8) * Cdim + n;
            if (addmat) {
                float2 a0 = *(const float2*)(addmat + o0);
                float2 a1 = *(const float2*)(addmat + o1);
                v0 += a0.x; v1 += a0.y; v2 += a1.x; v3 += a1.y;
            }
            if (outf) {
                *(float2*)(outf + o0) = make_float2(v0, v1);
                *(float2*)(outf + o1) = make_float2(v2, v3);
            }
            if (out_hi) {
                __nv_bfloat16 h0 = __float2bfloat16(v0), h1 = __float2bfloat16(v1);
                __nv_bfloat16 h2 = __float2bfloat16(v2), h3 = __float2bfloat16(v3);
                __nv_bfloat162 hh0; hh0.x = h0; hh0.y = h1;
                __nv_bfloat162 hh1; hh1.x = h2; hh1.y = h3;
                __nv_bfloat162 ll0, ll1;
                ll0.x = __float2bfloat16(v0 - __bfloat162float(h0));
                ll0.y = __float2bfloat16(v1 - __bfloat162float(h1));
                ll1.x = __float2bfloat16(v2 - __bfloat162float(h2));
                ll1.y = __float2bfloat16(v3 - __bfloat162float(h3));
                *(__nv_bfloat162*)(out_hi + o0) = hh0;
                *(__nv_bfloat162*)(out_hi + o1) = hh1;
                *(__nv_bfloat162*)(out_lo + o0) = ll0;
                *(__nv_bfloat162*)(out_lo + o1) = ll1;
            }
        }
    }
}

// ---------------------------------------------------------------------------
// fp32 -> bf16 hi/lo elementwise
// ---------------------------------------------------------------------------
__global__ __launch_bounds__(256) void cvt_kernel(
    const float* __restrict__ src, __nv_bfloat16* __restrict__ hi,
    __nv_bfloat16* __restrict__ lo, int n4)
{
    int i = blockIdx.x * 256 + threadIdx.x;
    if (i >= n4) return;
    float4 x = ((const float4*)src)[i];
    __nv_bfloat16 h0 = __float2bfloat16(x.x), h1 = __float2bfloat16(x.y);
    __nv_bfloat16 h2 = __float2bfloat16(x.z), h3 = __float2bfloat16(x.w);
    __nv_bfloat162 a, b, c, d;
    a.x = h0; a.y = h1; b.x = h2; b.y = h3;
    c.x = __float2bfloat16(x.x - __bfloat162float(h0));
    c.y = __float2bfloat16(x.y - __bfloat162float(h1));
    d.x = __float2bfloat16(x.z - __bfloat162float(h2));
    d.y = __float2bfloat16(x.w - __bfloat162float(h3));
    ((__nv_bfloat162*)hi)[2 * i] = a; ((__nv_bfloat162*)hi)[2 * i + 1] = b;
    ((__nv_bfloat162*)lo)[2 * i] = c; ((__nv_bfloat162*)lo)[2 * i + 1] = d;
}

// ---------------------------------------------------------------------------
// W[k][n] fp32 -> WT[n][k] bf16 hi/lo (transpose-convert)
// ---------------------------------------------------------------------------
__global__ __launch_bounds__(256) void wcvt_kernel(
    const float* __restrict__ W, __nv_bfloat16* __restrict__ Thi,
    __nv_bfloat16* __restrict__ Tlo)
{
    __shared__ float t[32][33];
    int tx = threadIdx.x & 31, ty = threadIdx.x >> 5;
    int n0 = blockIdx.x * 32, k0 = blockIdx.y * 32;
#pragma unroll
    for (int i = 0; i < 32; i += 8)
        t[ty + i][tx] = W[(size_t)(k0 + ty + i) * Cdim + n0 + tx];
    __syncthreads();
#pragma unroll
    for (int i = 0; i < 32; i += 8) {
        float v = t[tx][ty + i];
        __nv_bfloat16 h = __float2bfloat16(v);
        size_t o = (size_t)(n0 + ty + i) * Cdim + k0 + tx;
        Thi[o] = h;
        Tlo[o] = __float2bfloat16(v - __bfloat162float(h));
    }
}

// ---------------------------------------------------------------------------
// attention logits / softmax / pool
// ---------------------------------------------------------------------------
__global__ __launch_bounds__(256) void attn_logits_kernel(
    const float* __restrict__ A, const float* __restrict__ W16,
    const float* __restrict__ b16, const float* __restrict__ scalevec,
    float* __restrict__ logits)
{
    int warp = threadIdx.x >> 5, lane = threadIdx.x & 31;
    int row = blockIdx.x * 8 + warp;
    int n = row >> 12;
    const float* arow = A + (size_t)row * Cdim;
    const float* sv = scalevec ? scalevec + (size_t)n * Cdim : nullptr;

    float acc[16];
#pragma unroll
    for (int h = 0; h < 16; h++) acc[h] = 0.f;

    for (int c = lane; c < Cdim; c += 32) {
        float a = arow[c];
        if (sv) a *= sv[c];
        const float4* w4 = (const float4*)(W16 + (size_t)c * 16);
        float4 w0 = w4[0], w1 = w4[1], w2 = w4[2], w3 = w4[3];
        acc[0]  = fmaf(a, w0.x, acc[0]);  acc[1]  = fmaf(a, w0.y, acc[1]);
        acc[2]  = fmaf(a, w0.z, acc[2]);  acc[3]  = fmaf(a, w0.w, acc[3]);
        acc[4]  = fmaf(a, w1.x, acc[4]);  acc[5]  = fmaf(a, w1.y, acc[5]);
        acc[6]  = fmaf(a, w1.z, acc[6]);  acc[7]  = fmaf(a, w1.w, acc[7]);
        acc[8]  = fmaf(a, w2.x, acc[8]);  acc[9]  = fmaf(a, w2.y, acc[9]);
        acc[10] = fmaf(a, w2.z, acc[10]); acc[11] = fmaf(a, w2.w, acc[11]);
        acc[12] = fmaf(a, w3.x, acc[12]); acc[13] = fmaf(a, w3.y, acc[13]);
        acc[14] = fmaf(a, w3.z, acc[14]); acc[15] = fmaf(a, w3.w, acc[15]);
    }
#pragma unroll
    for (int h = 0; h < 16; h++) {
        float v = acc[h];
#pragma unroll
        for (int o = 16; o; o >>= 1) v += __shfl_xor_sync(0xffffffffu, v, o);
        if (lane == h) logits[(size_t)row * 16 + h] = (v + b16[h]) * ATT_SCALE;
    }
}

__global__ __launch_bounds__(256) void softmax_L_kernel(
    const float* __restrict__ logits, float* __restrict__ w_out)
{
    int n = blockIdx.x / Hn, h = blockIdx.x % Hn;
    __shared__ float buf[Lseq];
    __shared__ float red[256];
    int tid = threadIdx.x;

    float m = -1e30f;
    for (int l = tid; l < Lseq; l += 256) {
        float v = logits[((size_t)n * Lseq + l) * Hn + h];
        buf[l] = v;
        m = fmaxf(m, v);
    }
    red[tid] = m; __syncthreads();
    for (int s = 128; s; s >>= 1) {
        if (tid < s) red[tid] = fmaxf(red[tid], red[tid + s]);
        __syncthreads();
    }
    m = red[0]; __syncthreads();

    float sum = 0.f;
    for (int l = tid; l < Lseq; l += 256) {
        float e = __expf(buf[l] - m);
        buf[l] = e;
        sum += e;
    }
    red[tid] = sum; __syncthreads();
    for (int s = 128; s; s >>= 1) {
        if (tid < s) red[tid] += red[tid + s];
        __syncthreads();
    }
    float inv = 1.f / red[0];

    float* wp = w_out + ((size_t)n * Hn + h) * Lseq;
    for (int l = tid; l < Lseq; l += 256) wp[l] = buf[l] * inv;
}

__global__ __launch_bounds__(1024) void pool_kernel(
    const float* __restrict__ w, const float* __restrict__ A,
    float* __restrict__ pooled)
{
    int h = blockIdx.x, n = blockIdx.y;
    int tid = threadIdx.x;
    int dh = tid & 63, g = tid >> 6;

    const float* wp = w + ((size_t)n * Hn + h) * Lseq + g * 256;
    const float* ap = A + ((size_t)(n * Lseq + g * 256)) * Cdim + h * 64 + dh;

    float a0 = 0.f, a1 = 0.f, a2 = 0.f, a3 = 0.f;
    for (int l = 0; l < 256; l += 4) {
        a0 = fmaf(wp[l + 0], ap[(size_t)(l + 0) * Cdim], a0);
        a1 = fmaf(wp[l + 1], ap[(size_t)(l + 1) * Cdim], a1);
        a2 = fmaf(wp[l + 2], ap[(size_t)(l + 2) * Cdim], a2);
        a3 = fmaf(wp[l + 3], ap[(size_t)(l + 3) * Cdim], a3);
    }
    __shared__ float red[1024];
    red[tid] = a0 + a1 + a2 + a3;
    __syncthreads();
    if (tid < 64) {
        float s = 0.f;
#pragma unroll
        for (int gg = 0; gg < 16; gg++) s += red[dh + gg * 64];
        pooled[(size_t)n * Cdim + h * 64 + dh] = s;
    }
}

// ---------------------------------------------------------------------------
// Launch
// ---------------------------------------------------------------------------
extern "C" void kernel_launch(void* const* d_in, const int* in_sizes, int n_in,
                              void* d_out, int out_size)
{
    const float* x_q  = (const float*)d_in[0];
    const float* x_kv = (const float*)d_in[1];
    const float* Wq   = (const float*)d_in[2];
    const float* bq   = (const float*)d_in[3];
    const float* Wqa  = (const float*)d_in[4];
    const float* bqa  = (const float*)d_in[5];
    const float* Wk   = (const float*)d_in[6];
    const float* bk   = (const float*)d_in[7];
    const float* Wka  = (const float*)d_in[8];
    const float* bka  = (const float*)d_in[9];
    const float* Wv   = (const float*)d_in[10];
    const float* bv   = (const float*)d_in[11];
    const float* Wt   = (const float*)d_in[12];
    const float* bt   = (const float*)d_in[13];
    const float* Wp   = (const float*)d_in[14];
    const float* bp   = (const float*)d_in[15];
    float* out = (float*)d_out;

    float *Qb, *Kb, *lg, *wb, *pq, *pk;
    __nv_bfloat16 *xqh, *xql, *xkh, *xkl, *Vh, *Vl, *Th, *Tl, *WTh, *WTl;
    cudaGetSymbolAddress((void**)&Qb, g_Q);
    cudaGetSymbolAddress((void**)&Kb, g_K);
    cudaGetSymbolAddress((void**)&lg, g_logits);
    cudaGetSymbolAddress((void**)&wb, g_wbuf);
    cudaGetSymbolAddress((void**)&pq, g_pq);
    cudaGetSymbolAddress((void**)&pk, g_pk);
    cudaGetSymbolAddress((void**)&xqh, g_xq_hi);
    cudaGetSymbolAddress((void**)&xql, g_xq_lo);
    cudaGetSymbolAddress((void**)&xkh, g_xkv_hi);
    cudaGetSymbolAddress((void**)&xkl, g_xkv_lo);
    cudaGetSymbolAddress((void**)&Vh, g_V_hi);
    cudaGetSymbolAddress((void**)&Vl, g_V_lo);
    cudaGetSymbolAddress((void**)&Th, g_T_hi);
    cudaGetSymbolAddress((void**)&Tl, g_T_lo);
    cudaGetSymbolAddress((void**)&WTh, g_WT_hi);
    cudaGetSymbolAddress((void**)&WTl, g_WT_lo);

    const size_t WSZ = (size_t)Cdim * Cdim;
    __nv_bfloat16 *wqh = WTh + 0 * WSZ, *wqlv = WTl + 0 * WSZ;
    __nv_bfloat16 *wkh = WTh + 1 * WSZ, *wklv = WTl + 1 * WSZ;
    __nv_bfloat16 *wvh = WTh + 2 * WSZ, *wvlv = WTl + 2 * WSZ;
    __nv_bfloat16 *wth = WTh + 3 * WSZ, *wtlv = WTl + 3 * WSZ;
    __nv_bfloat16 *wph = WTh + 4 * WSZ, *wplv = WTl + 4 * WSZ;

    cudaFuncSetAttribute(mma_gemm, cudaFuncAttributeMaxDynamicSharedMemorySize, SMEMB);

    int n4 = Mrows * Cdim / 4;
    cvt_kernel<<<(n4 + 255) / 256, 256>>>(x_q, xqh, xql, n4);
    cvt_kernel<<<(n4 + 255) / 256, 256>>>(x_kv, xkh, xkl, n4);
    dim3 wg(32, 32);
    wcvt_kernel<<<wg, 256>>>(Wq, wqh, wqlv);
    wcvt_kernel<<<wg, 256>>>(Wk, wkh, wklv);
    wcvt_kernel<<<wg, 256>>>(Wv, wvh, wvlv);
    wcvt_kernel<<<wg, 256>>>(Wt, wth, wtlv);
    wcvt_kernel<<<wg, 256>>>(Wp, wph, wplv);

    dim3 gg(Cdim / 128, Mrows / 128);   // 8 x 256

    // 1. Q = x_q @ Wq + bq  (fp32)
    mma_gemm<<<gg, 256, SMEMB>>>(xqh, xql, wqh, wqlv, bq, nullptr, nullptr,
                                 Qb, nullptr, nullptr);
    // 2. q pooling
    attn_logits_kernel<<<Mrows / 8, 256>>>(Qb, Wqa, bqa, nullptr, lg);
    softmax_L_kernel<<<NB * Hn, 256>>>(lg, wb);
    pool_kernel<<<dim3(Hn, NB), 1024>>>(wb, Qb, pq);
    // 3. K = x_kv @ Wk + bk  (fp32)
    mma_gemm<<<gg, 256, SMEMB>>>(xkh, xkl, wkh, wklv, bk, nullptr, nullptr,
                                 Kb, nullptr, nullptr);
    // 4. k pooling (gated logits)
    attn_logits_kernel<<<Mrows / 8, 256>>>(Kb, Wka, bka, pq, lg);
    softmax_L_kernel<<<NB * Hn, 256>>>(lg, wb);
    pool_kernel<<<dim3(Hn, NB), 1024>>>(wb, Kb, pk);
    // 5. Vs = (x_kv @ Wv + bv) * pk[n,col]  (bf16 hi/lo only)
    mma_gemm<<<gg, 256, SMEMB>>>(xkh, xkl, wvh, wvlv, bv, pk, nullptr,
                                 nullptr, Vh, Vl);
    // 6. T = Vs @ Wt + bt + Q  (bf16 hi/lo only)
    mma_gemm<<<gg, 256, SMEMB>>>(Vh, Vl, wth, wtlv, bt, nullptr, Qb,
                                 nullptr, Th, Tl);
    // 7. out = T @ Wp + bp  (fp32)
    mma_gemm<<<gg, 256, SMEMB>>>(Th, Tl, wph, wplv, bp, nullptr, nullptr,
                                 out, nullptr, nullptr);
}

// round 5
// speedup vs baseline: 5.5503x; 1.2611x over previous
#include <cuda_runtime.h>
#include <cuda_fp16.h>
#include <cstdint>

#define Cdim 1024
#define Hn   16
#define NB   8
#define Lseq 4096
#define Mrows (NB * Lseq)      // 32768
#define ATT_SCALE 0.125f

// ---------------------------------------------------------------------------
// Scratch
// ---------------------------------------------------------------------------
__device__ float g_Q[(size_t)Mrows * Cdim];
__device__ float g_K[(size_t)Mrows * Cdim];
__device__ float g_logits[(size_t)Mrows * Hn];
__device__ float g_wbuf[(size_t)NB * Hn * Lseq];
__device__ float g_pq[NB * Cdim];
__device__ float g_pk[NB * Cdim];

__device__ __half g_xq_hi[(size_t)Mrows * Cdim];
__device__ __half g_xq_lo[(size_t)Mrows * Cdim];
__device__ __half g_xkv_hi[(size_t)Mrows * Cdim];
__device__ __half g_xkv_lo[(size_t)Mrows * Cdim];
__device__ __half g_V_hi[(size_t)Mrows * Cdim];
__device__ __half g_V_lo[(size_t)Mrows * Cdim];
__device__ __half g_T_hi[(size_t)Mrows * Cdim];
__device__ __half g_T_lo[(size_t)Mrows * Cdim];
// transposed (K-major, [n][k]) fp16 weights, 5 matrices
__device__ __half g_WT[5][(size_t)Cdim * Cdim];

// ---------------------------------------------------------------------------
// PTX helpers (family-safe: cp.async / ldmatrix / mma.sync only)
// ---------------------------------------------------------------------------
__device__ __forceinline__ uint32_t smem_u32(const void* p) {
    uint32_t a;
    asm("{ .reg .u64 t; cvta.to.shared.u64 t, %1; cvt.u32.u64 %0, t; }" : "=r"(a) : "l"(p));
    return a;
}
__device__ __forceinline__ void cpa16(uint32_t dst, const void* src) {
    asm volatile("cp.async.cg.shared.global [%0], [%1], 16;" :: "r"(dst), "l"(src) : "memory");
}
__device__ __forceinline__ void cpa_commit() {
    asm volatile("cp.async.commit_group;" ::: "memory");
}
__device__ __forceinline__ void cpa_wait2() {
    asm volatile("cp.async.wait_group 2;" ::: "memory");
}
__device__ __forceinline__ void ldm_x4(uint32_t* r, uint32_t addr) {
    asm volatile("ldmatrix.sync.aligned.m8n8.x4.shared.b16 {%0,%1,%2,%3}, [%4];"
                 : "=r"(r[0]), "=r"(r[1]), "=r"(r[2]), "=r"(r[3]) : "r"(addr));
}
__device__ __forceinline__ void mma_fp16(float* c, const uint32_t* a, const uint32_t* b) {
    asm volatile(
        "mma.sync.aligned.m16n8k16.row.col.f32.f16.f16.f32 "
        "{%0,%1,%2,%3}, {%4,%5,%6,%7}, {%8,%9}, {%0,%1,%2,%3};"
        : "+f"(c[0]), "+f"(c[1]), "+f"(c[2]), "+f"(c[3])
        : "r"(a[0]), "r"(a[1]), "r"(a[2]), "r"(a[3]), "r"(b[0]), "r"(b[1]));
}

// ---------------------------------------------------------------------------
// HMMA GEMM: out[M=32768, N=1024] = A[M,1024] @ W[1024,N] (+epilogues)
// A fp16 hi/lo row-major; W fp16 K-major (WT[n][k]).
// Block 128x128, BK=32, 4-stage cp.async, 8 warps of 64x32.
// 2-term split: Ahi*W + Alo*W.
// ---------------------------------------------------------------------------
#define ROWB   80                  // padded smem row stride (bytes) per 32 fp16
#define TILEB  (128 * ROWB)        // 10240 per operand tile
#define STAGEB (3 * TILEB)         // Ahi, Alo, B
#define STAGES 4
#define SMEMB  (STAGES * STAGEB)   // 122880

__device__ __forceinline__ void issue_stage(
    uint32_t sb, int s, int chunk, int tid,
    const __half* Ahi, const __half* Alo, const __half* Bw,
    int grow0, int ncol0)
{
    uint32_t stb = sb + (uint32_t)s * STAGEB;
    int k0 = chunk * 32;
#pragma unroll
    for (int j = 0; j < 6; j++) {
        int id = tid + j * 256;           // 0..1535
        int t4 = id >> 9;                 // operand tile 0..2
        int w  = id & 511;
        int r  = w >> 2, c = w & 3;       // row, 16B chunk
        const __half* src = (t4 == 0) ? Ahi : (t4 == 1) ? Alo : Bw;
        int rb = (t4 < 2) ? grow0 : ncol0;
        const void* g = src + ((size_t)(rb + r) * Cdim + k0 + c * 8);
        cpa16(stb + (uint32_t)t4 * TILEB + (uint32_t)(r * ROWB + c * 16), g);
    }
}

__global__ void __launch_bounds__(256, 1) mma_gemm(
    const __half* __restrict__ Ahi, const __half* __restrict__ Alo,
    const __half* __restrict__ Bw,
    const float* __restrict__ bias, const float* __restrict__ colscale,
    const float* __restrict__ addmat,
    float* __restrict__ outf,
    __half* __restrict__ out_hi, __half* __restrict__ out_lo)
{
    extern __shared__ char smem[];
    uint32_t sb = smem_u32(smem);
    int tid = threadIdx.x;
    int lane = tid & 31, wid = tid >> 5;
    int wm = wid & 1, wc = wid >> 1;           // warp 64x32 tile: 2 x 4 grid
    int bM = blockIdx.y * 128, bN = blockIdx.x * 128;

    float acc[4][4][4];
#pragma unroll
    for (int i = 0; i < 4; i++)
#pragma unroll
        for (int j = 0; j < 4; j++)
#pragma unroll
            for (int q = 0; q < 4; q++) acc[i][j][q] = 0.f;

    int grp = lane >> 3, l7 = lane & 7;
    uint32_t a_off = (uint32_t)((l7 + ((grp & 1) << 3)) * ROWB + ((grp >> 1) << 4));
    uint32_t b_off = (uint32_t)((l7 + ((grp >> 1) << 3)) * ROWB + ((grp & 1) << 4));

    // prologue
#pragma unroll
    for (int s = 0; s < 3; s++) {
        issue_stage(sb, s, s, tid, Ahi, Alo, Bw, bM, bN);
        cpa_commit();
    }

    for (int k = 0; k < 32; k++) {
        cpa_wait2();
        __syncthreads();
        if (k + 3 < 32)
            issue_stage(sb, (k + 3) & 3, k + 3, tid, Ahi, Alo, Bw, bM, bN);
        cpa_commit();

        uint32_t st = sb + (uint32_t)(k & 3) * STAGEB;
#pragma unroll
        for (int kk = 0; kk < 2; kk++) {
            uint32_t kb = (uint32_t)(kk * 32);
            uint32_t bh[8];
#pragma unroll
            for (int h = 0; h < 2; h++) {
                uint32_t nrow = (uint32_t)((wc * 32 + h * 16) * ROWB);
                ldm_x4(bh + h * 4, st + 2 * TILEB + nrow + b_off + kb);
            }
#pragma unroll
            for (int mt = 0; mt < 4; mt++) {
                uint32_t mrow = (uint32_t)((wm * 64 + mt * 16) * ROWB);
                uint32_t ah[4], al[4];
                ldm_x4(ah, st + 0 * TILEB + mrow + a_off + kb);
                ldm_x4(al, st + 1 * TILEB + mrow + a_off + kb);
#pragma unroll
                for (int nt = 0; nt < 4; nt++) {
                    mma_fp16(acc[mt][nt], ah, &bh[nt * 2]);
                    mma_fp16(acc[mt][nt], al, &bh[nt * 2]);
                }
            }
        }
    }

    // ---------------- epilogue ----------------
    int nidx = bM >> 12;
#pragma unroll
    for (int mt = 0; mt < 4; mt++) {
        int m0 = bM + wm * 64 + mt * 16 + (lane >> 2);
#pragma unroll
        for (int nt = 0; nt < 4; nt++) {
            int n = bN + wc * 32 + nt * 8 + (lane & 3) * 2;
            float b0 = bias[n], b1 = bias[n + 1];
            float v0 = acc[mt][nt][0] + b0, v1 = acc[mt][nt][1] + b1;
            float v2 = acc[mt][nt][2] + b0, v3 = acc[mt][nt][3] + b1;
            if (colscale) {
                float s0 = colscale[nidx * Cdim + n];
                float s1 = colscale[nidx * Cdim + n + 1];
                v0 *= s0; v1 *= s1; v2 *= s0; v3 *= s1;
            }
            size_t o0 = (size_t)m0 * Cdim + n;
            size_t o1 = (size_t)(m0 + 8) * Cdim + n;
            if (addmat) {
                float2 a0 = *(const float2*)(addmat + o0);
                float2 a1 = *(const float2*)(addmat + o1);
                v0 += a0.x; v1 += a0.y; v2 += a1.x; v3 += a1.y;
            }
            if (outf) {
                *(float2*)(outf + o0) = make_float2(v0, v1);
                *(float2*)(outf + o1) = make_float2(v2, v3);
            }
            if (out_hi) {
                __half h0 = __float2half(v0), h1 = __float2half(v1);
                __half h2 = __float2half(v2), h3 = __float2half(v3);
                __half2 hh0 = __halves2half2(h0, h1);
                __half2 hh1 = __halves2half2(h2, h3);
                __half2 ll0 = __halves2half2(
                    __float2half(v0 - __half2float(h0)),
                    __float2half(v1 - __half2float(h1)));
                __half2 ll1 = __halves2half2(
                    __float2half(v2 - __half2float(h2)),
                    __float2half(v3 - __half2float(h3)));
                *(__half2*)(out_hi + o0) = hh0;
                *(__half2*)(out_hi + o1) = hh1;
                *(__half2*)(out_lo + o0) = ll0;
                *(__half2*)(out_lo + o1) = ll1;
            }
        }
    }
}

// ---------------------------------------------------------------------------
// fp32 -> fp16 hi/lo elementwise
// ---------------------------------------------------------------------------
__global__ __launch_bounds__(256) void cvt_kernel(
    const float* __restrict__ src, __half* __restrict__ hi,
    __half* __restrict__ lo, int n4)
{
    int i = blockIdx.x * 256 + threadIdx.x;
    if (i >= n4) return;
    float4 x = ((const float4*)src)[i];
    __half h0 = __float2half(x.x), h1 = __float2half(x.y);
    __half h2 = __float2half(x.z), h3 = __float2half(x.w);
    __half2 a = __halves2half2(h0, h1);
    __half2 b = __halves2half2(h2, h3);
    __half2 c = __halves2half2(__float2half(x.x - __half2float(h0)),
                               __float2half(x.y - __half2float(h1)));
    __half2 d = __halves2half2(__float2half(x.z - __half2float(h2)),
                               __float2half(x.w - __half2float(h3)));
    ((__half2*)hi)[2 * i] = a; ((__half2*)hi)[2 * i + 1] = b;
    ((__half2*)lo)[2 * i] = c; ((__half2*)lo)[2 * i + 1] = d;
}

// ---------------------------------------------------------------------------
// W[k][n] fp32 -> WT[n][k] fp16 (transpose-convert)
// ---------------------------------------------------------------------------
__global__ __launch_bounds__(256) void wcvt_kernel(
    const float* __restrict__ W, __half* __restrict__ T16)
{
    __shared__ float t[32][33];
    int tx = threadIdx.x & 31, ty = threadIdx.x >> 5;
    int n0 = blockIdx.x * 32, k0 = blockIdx.y * 32;
#pragma unroll
    for (int i = 0; i < 32; i += 8)
        t[ty + i][tx] = W[(size_t)(k0 + ty + i) * Cdim + n0 + tx];
    __syncthreads();
#pragma unroll
    for (int i = 0; i < 32; i += 8) {
        size_t o = (size_t)(n0 + ty + i) * Cdim + k0 + tx;
        T16[o] = __float2half(t[tx][ty + i]);
    }
}

// ---------------------------------------------------------------------------
// attention logits / softmax / pool
// ---------------------------------------------------------------------------
__global__ __launch_bounds__(256) void attn_logits_kernel(
    const float* __restrict__ A, const float* __restrict__ W16,
    const float* __restrict__ b16, const float* __restrict__ scalevec,
    float* __restrict__ logits)
{
    int warp = threadIdx.x >> 5, lane = threadIdx.x & 31;
    int row = blockIdx.x * 8 + warp;
    int n = row >> 12;
    const float* arow = A + (size_t)row * Cdim;
    const float* sv = scalevec ? scalevec + (size_t)n * Cdim : nullptr;

    float acc[16];
#pragma unroll
    for (int h = 0; h < 16; h++) acc[h] = 0.f;

    for (int c = lane; c < Cdim; c += 32) {
        float a = arow[c];
        if (sv) a *= sv[c];
        const float4* w4 = (const float4*)(W16 + (size_t)c * 16);
        float4 w0 = w4[0], w1 = w4[1], w2 = w4[2], w3 = w4[3];
        acc[0]  = fmaf(a, w0.x, acc[0]);  acc[1]  = fmaf(a, w0.y, acc[1]);
        acc[2]  = fmaf(a, w0.z, acc[2]);  acc[3]  = fmaf(a, w0.w, acc[3]);
        acc[4]  = fmaf(a, w1.x, acc[4]);  acc[5]  = fmaf(a, w1.y, acc[5]);
        acc[6]  = fmaf(a, w1.z, acc[6]);  acc[7]  = fmaf(a, w1.w, acc[7]);
        acc[8]  = fmaf(a, w2.x, acc[8]);  acc[9]  = fmaf(a, w2.y, acc[9]);
        acc[10] = fmaf(a, w2.z, acc[10]); acc[11] = fmaf(a, w2.w, acc[11]);
        acc[12] = fmaf(a, w3.x, acc[12]); acc[13] = fmaf(a, w3.y, acc[13]);
        acc[14] = fmaf(a, w3.z, acc[14]); acc[15] = fmaf(a, w3.w, acc[15]);
    }
#pragma unroll
    for (int h = 0; h < 16; h++) {
        float v = acc[h];
#pragma unroll
        for (int o = 16; o; o >>= 1) v += __shfl_xor_sync(0xffffffffu, v, o);
        if (lane == h) logits[(size_t)row * 16 + h] = (v + b16[h]) * ATT_SCALE;
    }
}

__global__ __launch_bounds__(256) void softmax_L_kernel(
    const float* __restrict__ logits, float* __restrict__ w_out)
{
    int n = blockIdx.x / Hn, h = blockIdx.x % Hn;
    __shared__ float buf[Lseq];
    __shared__ float red[256];
    int tid = threadIdx.x;

    float m = -1e30f;
    for (int l = tid; l < Lseq; l += 256) {
        float v = logits[((size_t)n * Lseq + l) * Hn + h];
        buf[l] = v;
        m = fmaxf(m, v);
    }
    red[tid] = m; __syncthreads();
    for (int s = 128; s; s >>= 1) {
        if (tid < s) red[tid] = fmaxf(red[tid], red[tid + s]);
        __syncthreads();
    }
    m = red[0]; __syncthreads();

    float sum = 0.f;
    for (int l = tid; l < Lseq; l += 256) {
        float e = __expf(buf[l] - m);
        buf[l] = e;
        sum += e;
    }
    red[tid] = sum; __syncthreads();
    for (int s = 128; s; s >>= 1) {
        if (tid < s) red[tid] += red[tid + s];
        __syncthreads();
    }
    float inv = 1.f / red[0];

    float* wp = w_out + ((size_t)n * Hn + h) * Lseq;
    for (int l = tid; l < Lseq; l += 256) wp[l] = buf[l] * inv;
}

__global__ __launch_bounds__(1024) void pool_kernel(
    const float* __restrict__ w, const float* __restrict__ A,
    float* __restrict__ pooled)
{
    int h = blockIdx.x, n = blockIdx.y;
    int tid = threadIdx.x;
    int dh = tid & 63, g = tid >> 6;

    const float* wp = w + ((size_t)n * Hn + h) * Lseq + g * 256;
    const float* ap = A + ((size_t)(n * Lseq + g * 256)) * Cdim + h * 64 + dh;

    float a0 = 0.f, a1 = 0.f, a2 = 0.f, a3 = 0.f;
    for (int l = 0; l < 256; l += 4) {
        a0 = fmaf(wp[l + 0], ap[(size_t)(l + 0) * Cdim], a0);
        a1 = fmaf(wp[l + 1], ap[(size_t)(l + 1) * Cdim], a1);
        a2 = fmaf(wp[l + 2], ap[(size_t)(l + 2) * Cdim], a2);
        a3 = fmaf(wp[l + 3], ap[(size_t)(l + 3) * Cdim], a3);
    }
    __shared__ float red[1024];
    red[tid] = a0 + a1 + a2 + a3;
    __syncthreads();
    if (tid < 64) {
        float s = 0.f;
#pragma unroll
        for (int gg = 0; gg < 16; gg++) s += red[dh + gg * 64];
        pooled[(size_t)n * Cdim + h * 64 + dh] = s;
    }
}

// ---------------------------------------------------------------------------
// Launch
// ---------------------------------------------------------------------------
extern "C" void kernel_launch(void* const* d_in, const int* in_sizes, int n_in,
                              void* d_out, int out_size)
{
    const float* x_q  = (const float*)d_in[0];
    const float* x_kv = (const float*)d_in[1];
    const float* Wq   = (const float*)d_in[2];
    const float* bq   = (const float*)d_in[3];
    const float* Wqa  = (const float*)d_in[4];
    const float* bqa  = (const float*)d_in[5];
    const float* Wk   = (const float*)d_in[6];
    const float* bk   = (const float*)d_in[7];
    const float* Wka  = (const float*)d_in[8];
    const float* bka  = (const float*)d_in[9];
    const float* Wv   = (const float*)d_in[10];
    const float* bv   = (const float*)d_in[11];
    const float* Wt   = (const float*)d_in[12];
    const float* bt   = (const float*)d_in[13];
    const float* Wp   = (const float*)d_in[14];
    const float* bp   = (const float*)d_in[15];
    float* out = (float*)d_out;

    float *Qb, *Kb, *lg, *wb, *pq, *pk;
    __half *xqh, *xql, *xkh, *xkl, *Vh, *Vl, *Th, *Tl, *WT;
    cudaGetSymbolAddress((void**)&Qb, g_Q);
    cudaGetSymbolAddress((void**)&Kb, g_K);
    cudaGetSymbolAddress((void**)&lg, g_logits);
    cudaGetSymbolAddress((void**)&wb, g_wbuf);
    cudaGetSymbolAddress((void**)&pq, g_pq);
    cudaGetSymbolAddress((void**)&pk, g_pk);
    cudaGetSymbolAddress((void**)&xqh, g_xq_hi);
    cudaGetSymbolAddress((void**)&xql, g_xq_lo);
    cudaGetSymbolAddress((void**)&xkh, g_xkv_hi);
    cudaGetSymbolAddress((void**)&xkl, g_xkv_lo);
    cudaGetSymbolAddress((void**)&Vh, g_V_hi);
    cudaGetSymbolAddress((void**)&Vl, g_V_lo);
    cudaGetSymbolAddress((void**)&Th, g_T_hi);
    cudaGetSymbolAddress((void**)&Tl, g_T_lo);
    cudaGetSymbolAddress((void**)&WT, g_WT);

    const size_t WSZ = (size_t)Cdim * Cdim;
    __half *wq16 = WT + 0 * WSZ, *wk16 = WT + 1 * WSZ, *wv16 = WT + 2 * WSZ;
    __half *wt16 = WT + 3 * WSZ, *wp16 = WT + 4 * WSZ;

    cudaFuncSetAttribute(mma_gemm, cudaFuncAttributeMaxDynamicSharedMemorySize, SMEMB);

    int n4 = Mrows * Cdim / 4;
    cvt_kernel<<<(n4 + 255) / 256, 256>>>(x_q, xqh, xql, n4);
    cvt_kernel<<<(n4 + 255) / 256, 256>>>(x_kv, xkh, xkl, n4);
    dim3 wg(32, 32);
    wcvt_kernel<<<wg, 256>>>(Wq, wq16);
    wcvt_kernel<<<wg, 256>>>(Wk, wk16);
    wcvt_kernel<<<wg, 256>>>(Wv, wv16);
    wcvt_kernel<<<wg, 256>>>(Wt, wt16);
    wcvt_kernel<<<wg, 256>>>(Wp, wp16);

    dim3 gg(Cdim / 128, Mrows / 128);   // 8 x 256

    // 1. Q = x_q @ Wq + bq  (fp32)
    mma_gemm<<<gg, 256, SMEMB>>>(xqh, xql, wq16, bq, nullptr, nullptr,
                                 Qb, nullptr, nullptr);
    // 2. q pooling
    attn_logits_kernel<<<Mrows / 8, 256>>>(Qb, Wqa, bqa, nullptr, lg);
    softmax_L_kernel<<<NB * Hn, 256>>>(lg, wb);
    pool_kernel<<<dim3(Hn, NB), 1024>>>(wb, Qb, pq);
    // 3. K = x_kv @ Wk + bk  (fp32)
    mma_gemm<<<gg, 256, SMEMB>>>(xkh, xkl, wk16, bk, nullptr, nullptr,
                                 Kb, nullptr, nullptr);
    // 4. k pooling (gated logits)
    attn_logits_kernel<<<Mrows / 8, 256>>>(Kb, Wka, bka, pq, lg);
    softmax_L_kernel<<<NB * Hn, 256>>>(lg, wb);
    pool_kernel<<<dim3(Hn, NB), 1024>>>(wb, Kb, pk);
    // 5. Vs = (x_kv @ Wv + bv) * pk[n,col]  (fp16 hi/lo only)
    mma_gemm<<<gg, 256, SMEMB>>>(xkh, xkl, wv16, bv, pk, nullptr,
                                 nullptr, Vh, Vl);
    // 6. T = Vs @ Wt + bt + Q  (fp16 hi/lo only)
    mma_gemm<<<gg, 256, SMEMB>>>(Vh, Vl, wt16, bt, nullptr, Qb,
                                 nullptr, Th, Tl);
    // 7. out = T @ Wp + bp  (fp32)
    mma_gemm<<<gg, 256, SMEMB>>>(Th, Tl, wp16, bp, nullptr, nullptr,
                                 out, nullptr, nullptr);
}

// round 6
// speedup vs baseline: 6.0580x; 1.0915x over previous
#include <cuda_runtime.h>
#include <cuda_fp16.h>
#include <cstdint>

#define Cdim 1024
#define Hn   16
#define NB   8
#define Lseq 4096
#define Mrows (NB * Lseq)      // 32768
#define ATT_SCALE 0.125f

// ---------------------------------------------------------------------------
// Scratch
// ---------------------------------------------------------------------------
__device__ float g_Q[(size_t)Mrows * Cdim];
__device__ float g_K[(size_t)Mrows * Cdim];
__device__ float g_logits[(size_t)Mrows * Hn];
__device__ float g_wbuf[(size_t)NB * Hn * Lseq];
__device__ float g_pq[NB * Cdim];
__device__ float g_pk[NB * Cdim];

__device__ __half g_xq_hi[(size_t)Mrows * Cdim];
__device__ __half g_xq_lo[(size_t)Mrows * Cdim];
__device__ __half g_xkv_hi[(size_t)Mrows * Cdim];
__device__ __half g_xkv_lo[(size_t)Mrows * Cdim];
__device__ __half g_V_hi[(size_t)Mrows * Cdim];
__device__ __half g_V_lo[(size_t)Mrows * Cdim];
__device__ __half g_T_hi[(size_t)Mrows * Cdim];
__device__ __half g_T_lo[(size_t)Mrows * Cdim];
__device__ __half g_WT[5][(size_t)Cdim * Cdim];

// ---------------------------------------------------------------------------
// PTX helpers
// ---------------------------------------------------------------------------
__device__ __forceinline__ uint32_t smem_u32(const void* p) {
    uint32_t a;
    asm("{ .reg .u64 t; cvta.to.shared.u64 t, %1; cvt.u32.u64 %0, t; }" : "=r"(a) : "l"(p));
    return a;
}
__device__ __forceinline__ void cpa16(uint32_t dst, const void* src) {
    asm volatile("cp.async.cg.shared.global [%0], [%1], 16;" :: "r"(dst), "l"(src) : "memory");
}
__device__ __forceinline__ void cpa_commit() {
    asm volatile("cp.async.commit_group;" ::: "memory");
}
__device__ __forceinline__ void cpa_wait1() {
    asm volatile("cp.async.wait_group 1;" ::: "memory");
}
__device__ __forceinline__ void ldm_x4(uint32_t* r, uint32_t addr) {
    asm volatile("ldmatrix.sync.aligned.m8n8.x4.shared.b16 {%0,%1,%2,%3}, [%4];"
                 : "=r"(r[0]), "=r"(r[1]), "=r"(r[2]), "=r"(r[3]) : "r"(addr));
}
__device__ __forceinline__ void mma_fp16(float* c, const uint32_t* a, const uint32_t* b) {
    asm volatile(
        "mma.sync.aligned.m16n8k16.row.col.f32.f16.f16.f32 "
        "{%0,%1,%2,%3}, {%4,%5,%6,%7}, {%8,%9}, {%0,%1,%2,%3};"
        : "+f"(c[0]), "+f"(c[1]), "+f"(c[2]), "+f"(c[3])
        : "r"(a[0]), "r"(a[1]), "r"(a[2]), "r"(a[3]), "r"(b[0]), "r"(b[1]));
}

// ---------------------------------------------------------------------------
// HMMA GEMM: out[M,1024] = A[M,1024] @ W[1024,1024] (+epilogues)
// A fp16 hi/lo row-major; W fp16 K-major. Block 128x128, BK=64, 3 stages.
// ---------------------------------------------------------------------------
#define ROWB   144                 // 64 fp16 = 128B data + 16B pad
#define TILEB  (128 * ROWB)        // 18432
#define STAGEB (3 * TILEB)         // Ahi, Alo, B  -> 55296
#define STAGES 3
#define SMEMB  (STAGES * STAGEB)   // 165888

__device__ __forceinline__ void issue_stage(
    uint32_t sb, int s, int chunk, int tid,
    const __half* Ahi, const __half* Alo, const __half* Bw,
    int grow0, int ncol0)
{
    uint32_t stb = sb + (uint32_t)s * STAGEB;
    int k0 = chunk * 64;
#pragma unroll
    for (int j = 0; j < 12; j++) {
        int id = tid + j * 256;            // 0..3071
        int t4 = id >> 10;                 // operand tile 0..2
        int w  = id & 1023;
        int r  = w >> 3, c = w & 7;        // row, 16B chunk
        const __half* src = (t4 == 0) ? Ahi : (t4 == 1) ? Alo : Bw;
        int rb = (t4 < 2) ? grow0 : ncol0;
        const void* g = src + ((size_t)(rb + r) * Cdim + k0 + c * 8);
        cpa16(stb + (uint32_t)t4 * TILEB + (uint32_t)(r * ROWB + c * 16), g);
    }
}

__global__ void __launch_bounds__(256, 1) mma_gemm(
    const __half* __restrict__ Ahi, const __half* __restrict__ Alo,
    const __half* __restrict__ Bw,
    const float* __restrict__ bias, const float* __restrict__ colscale,
    const float* __restrict__ addmat,
    float* __restrict__ outf,
    __half* __restrict__ out_hi, __half* __restrict__ out_lo)
{
    extern __shared__ char smem[];
    uint32_t sb = smem_u32(smem);
    int tid = threadIdx.x;
    int lane = tid & 31, wid = tid >> 5;
    int wm = wid & 1, wc = wid >> 1;           // warp 64x32 tile: 2 x 4 grid
    int bM = blockIdx.y * 128, bN = blockIdx.x * 128;

    float acc[4][4][4];
#pragma unroll
    for (int i = 0; i < 4; i++)
#pragma unroll
        for (int j = 0; j < 4; j++)
#pragma unroll
            for (int q = 0; q < 4; q++) acc[i][j][q] = 0.f;

    int grp = lane >> 3, l7 = lane & 7;
    uint32_t a_off = (uint32_t)((l7 + ((grp & 1) << 3)) * ROWB + ((grp >> 1) << 4));
    uint32_t b_off = (uint32_t)((l7 + ((grp >> 1) << 3)) * ROWB + ((grp & 1) << 4));

    // prologue: 2 chunks
#pragma unroll
    for (int s = 0; s < 2; s++) {
        issue_stage(sb, s, s, tid, Ahi, Alo, Bw, bM, bN);
        cpa_commit();
    }

    for (int k = 0; k < 16; k++) {
        cpa_wait1();
        __syncthreads();
        if (k + 2 < 16)
            issue_stage(sb, (k + 2) % 3, k + 2, tid, Ahi, Alo, Bw, bM, bN);
        cpa_commit();

        uint32_t st = sb + (uint32_t)(k % 3) * STAGEB;
#pragma unroll
        for (int kk = 0; kk < 4; kk++) {
            uint32_t kb = (uint32_t)(kk * 32);
            uint32_t bh[8];
#pragma unroll
            for (int h = 0; h < 2; h++) {
                uint32_t nrow = (uint32_t)((wc * 32 + h * 16) * ROWB);
                ldm_x4(bh + h * 4, st + 2 * TILEB + nrow + b_off + kb);
            }
#pragma unroll
            for (int mt = 0; mt < 4; mt++) {
                uint32_t mrow = (uint32_t)((wm * 64 + mt * 16) * ROWB);
                uint32_t ah[4], al[4];
                ldm_x4(ah, st + 0 * TILEB + mrow + a_off + kb);
                ldm_x4(al, st + 1 * TILEB + mrow + a_off + kb);
#pragma unroll
                for (int nt = 0; nt < 4; nt++) {
                    mma_fp16(acc[mt][nt], ah, &bh[nt * 2]);
                    mma_fp16(acc[mt][nt], al, &bh[nt * 2]);
                }
            }
        }
    }

    // ---------------- epilogue ----------------
    int nidx = bM >> 12;
#pragma unroll
    for (int mt = 0; mt < 4; mt++) {
        int m0 = bM + wm * 64 + mt * 16 + (lane >> 2);
#pragma unroll
        for (int nt = 0; nt < 4; nt++) {
            int n = bN + wc * 32 + nt * 8 + (lane & 3) * 2;
            float b0 = bias[n], b1 = bias[n + 1];
            float v0 = acc[mt][nt][0] + b0, v1 = acc[mt][nt][1] + b1;
            float v2 = acc[mt][nt][2] + b0, v3 = acc[mt][nt][3] + b1;
            if (colscale) {
                float s0 = colscale[nidx * Cdim + n];
                float s1 = colscale[nidx * Cdim + n + 1];
                v0 *= s0; v1 *= s1; v2 *= s0; v3 *= s1;
            }
            size_t o0 = (size_t)m0 * Cdim + n;
            size_t o1 = (size_t)(m0 + 8) * Cdim + n;
            if (addmat) {
                float2 a0 = *(const float2*)(addmat + o0);
                float2 a1 = *(const float2*)(addmat + o1);
                v0 += a0.x; v1 += a0.y; v2 += a1.x; v3 += a1.y;
            }
            if (outf) {
                *(float2*)(outf + o0) = make_float2(v0, v1);
                *(float2*)(outf + o1) = make_float2(v2, v3);
            }
            if (out_hi) {
                __half h0 = __float2half(v0), h1 = __float2half(v1);
                __half h2 = __float2half(v2), h3 = __float2half(v3);
                __half2 hh0 = __halves2half2(h0, h1);
                __half2 hh1 = __halves2half2(h2, h3);
                __half2 ll0 = __halves2half2(
                    __float2half(v0 - __half2float(h0)),
                    __float2half(v1 - __half2float(h1)));
                __half2 ll1 = __halves2half2(
                    __float2half(v2 - __half2float(h2)),
                    __float2half(v3 - __half2float(h3)));
                *(__half2*)(out_hi + o0) = hh0;
                *(__half2*)(out_hi + o1) = hh1;
                *(__half2*)(out_lo + o0) = ll0;
                *(__half2*)(out_lo + o1) = ll1;
            }
        }
    }
}

// ---------------------------------------------------------------------------
// fp32 -> fp16 hi/lo elementwise
// ---------------------------------------------------------------------------
__global__ __launch_bounds__(256) void cvt_kernel(
    const float* __restrict__ src, __half* __restrict__ hi,
    __half* __restrict__ lo, int n4)
{
    int i = blockIdx.x * 256 + threadIdx.x;
    if (i >= n4) return;
    float4 x = ((const float4*)src)[i];
    __half h0 = __float2half(x.x), h1 = __float2half(x.y);
    __half h2 = __float2half(x.z), h3 = __float2half(x.w);
    __half2 a = __halves2half2(h0, h1);
    __half2 b = __halves2half2(h2, h3);
    __half2 c = __halves2half2(__float2half(x.x - __half2float(h0)),
                               __float2half(x.y - __half2float(h1)));
    __half2 d = __halves2half2(__float2half(x.z - __half2float(h2)),
                               __float2half(x.w - __half2float(h3)));
    ((__half2*)hi)[2 * i] = a; ((__half2*)hi)[2 * i + 1] = b;
    ((__half2*)lo)[2 * i] = c; ((__half2*)lo)[2 * i + 1] = d;
}

// ---------------------------------------------------------------------------
// W[k][n] fp32 -> WT[n][k] fp16 (transpose-convert)
// ---------------------------------------------------------------------------
__global__ __launch_bounds__(256) void wcvt_kernel(
    const float* __restrict__ W, __half* __restrict__ T16)
{
    __shared__ float t[32][33];
    int tx = threadIdx.x & 31, ty = threadIdx.x >> 5;
    int n0 = blockIdx.x * 32, k0 = blockIdx.y * 32;
#pragma unroll
    for (int i = 0; i < 32; i += 8)
        t[ty + i][tx] = W[(size_t)(k0 + ty + i) * Cdim + n0 + tx];
    __syncthreads();
#pragma unroll
    for (int i = 0; i < 32; i += 8) {
        size_t o = (size_t)(n0 + ty + i) * Cdim + k0 + tx;
        T16[o] = __float2half(t[tx][ty + i]);
    }
}

// ---------------------------------------------------------------------------
// attention logits / softmax / pool
// ---------------------------------------------------------------------------
__global__ __launch_bounds__(256) void attn_logits_kernel(
    const float* __restrict__ A, const float* __restrict__ W16,
    const float* __restrict__ b16, const float* __restrict__ scalevec,
    float* __restrict__ logits)
{
    int warp = threadIdx.x >> 5, lane = threadIdx.x & 31;
    int row = blockIdx.x * 8 + warp;
    int n = row >> 12;
    const float* arow = A + (size_t)row * Cdim;
    const float* sv = scalevec ? scalevec + (size_t)n * Cdim : nullptr;

    float acc[16];
#pragma unroll
    for (int h = 0; h < 16; h++) acc[h] = 0.f;

    for (int c = lane; c < Cdim; c += 32) {
        float a = arow[c];
        if (sv) a *= sv[c];
        const float4* w4 = (const float4*)(W16 + (size_t)c * 16);
        float4 w0 = w4[0], w1 = w4[1], w2 = w4[2], w3 = w4[3];
        acc[0]  = fmaf(a, w0.x, acc[0]);  acc[1]  = fmaf(a, w0.y, acc[1]);
        acc[2]  = fmaf(a, w0.z, acc[2]);  acc[3]  = fmaf(a, w0.w, acc[3]);
        acc[4]  = fmaf(a, w1.x, acc[4]);  acc[5]  = fmaf(a, w1.y, acc[5]);
        acc[6]  = fmaf(a, w1.z, acc[6]);  acc[7]  = fmaf(a, w1.w, acc[7]);
        acc[8]  = fmaf(a, w2.x, acc[8]);  acc[9]  = fmaf(a, w2.y, acc[9]);
        acc[10] = fmaf(a, w2.z, acc[10]); acc[11] = fmaf(a, w2.w, acc[11]);
        acc[12] = fmaf(a, w3.x, acc[12]); acc[13] = fmaf(a, w3.y, acc[13]);
        acc[14] = fmaf(a, w3.z, acc[14]); acc[15] = fmaf(a, w3.w, acc[15]);
    }
#pragma unroll
    for (int h = 0; h < 16; h++) {
        float v = acc[h];
#pragma unroll
        for (int o = 16; o; o >>= 1) v += __shfl_xor_sync(0xffffffffu, v, o);
        if (lane == h) logits[(size_t)row * 16 + h] = (v + b16[h]) * ATT_SCALE;
    }
}

__global__ __launch_bounds__(256) void softmax_L_kernel(
    const float* __restrict__ logits, float* __restrict__ w_out)
{
    int n = blockIdx.x / Hn, h = blockIdx.x % Hn;
    __shared__ float buf[Lseq];
    __shared__ float red[256];
    int tid = threadIdx.x;

    float m = -1e30f;
    for (int l = tid; l < Lseq; l += 256) {
        float v = logits[((size_t)n * Lseq + l) * Hn + h];
        buf[l] = v;
        m = fmaxf(m, v);
    }
    red[tid] = m; __syncthreads();
    for (int s = 128; s; s >>= 1) {
        if (tid < s) red[tid] = fmaxf(red[tid], red[tid + s]);
        __syncthreads();
    }
    m = red[0]; __syncthreads();

    float sum = 0.f;
    for (int l = tid; l < Lseq; l += 256) {
        float e = __expf(buf[l] - m);
        buf[l] = e;
        sum += e;
    }
    red[tid] = sum; __syncthreads();
    for (int s = 128; s; s >>= 1) {
        if (tid < s) red[tid] += red[tid + s];
        __syncthreads();
    }
    float inv = 1.f / red[0];

    float* wp = w_out + ((size_t)n * Hn + h) * Lseq;
    for (int l = tid; l < Lseq; l += 256) wp[l] = buf[l] * inv;
}

__global__ __launch_bounds__(1024) void pool_kernel(
    const float* __restrict__ w, const float* __restrict__ A,
    float* __restrict__ pooled)
{
    int h = blockIdx.x, n = blockIdx.y;
    int tid = threadIdx.x;
    int dh = tid & 63, g = tid >> 6;

    const float* wp = w + ((size_t)n * Hn + h) * Lseq + g * 256;
    const float* ap = A + ((size_t)(n * Lseq + g * 256)) * Cdim + h * 64 + dh;

    float a0 = 0.f, a1 = 0.f, a2 = 0.f, a3 = 0.f;
    for (int l = 0; l < 256; l += 4) {
        a0 = fmaf(wp[l + 0], ap[(size_t)(l + 0) * Cdim], a0);
        a1 = fmaf(wp[l + 1], ap[(size_t)(l + 1) * Cdim], a1);
        a2 = fmaf(wp[l + 2], ap[(size_t)(l + 2) * Cdim], a2);
        a3 = fmaf(wp[l + 3], ap[(size_t)(l + 3) * Cdim], a3);
    }
    __shared__ float red[1024];
    red[tid] = a0 + a1 + a2 + a3;
    __syncthreads();
    if (tid < 64) {
        float s = 0.f;
#pragma unroll
        for (int gg = 0; gg < 16; gg++) s += red[dh + gg * 64];
        pooled[(size_t)n * Cdim + h * 64 + dh] = s;
    }
}

// ---------------------------------------------------------------------------
// Launch
// ---------------------------------------------------------------------------
extern "C" void kernel_launch(void* const* d_in, const int* in_sizes, int n_in,
                              void* d_out, int out_size)
{
    const float* x_q  = (const float*)d_in[0];
    const float* x_kv = (const float*)d_in[1];
    const float* Wq   = (const float*)d_in[2];
    const float* bq   = (const float*)d_in[3];
    const float* Wqa  = (const float*)d_in[4];
    const float* bqa  = (const float*)d_in[5];
    const float* Wk   = (const float*)d_in[6];
    const float* bk   = (const float*)d_in[7];
    const float* Wka  = (const float*)d_in[8];
    const float* bka  = (const float*)d_in[9];
    const float* Wv   = (const float*)d_in[10];
    const float* bv   = (const float*)d_in[11];
    const float* Wt   = (const float*)d_in[12];
    const float* bt   = (const float*)d_in[13];
    const float* Wp   = (const float*)d_in[14];
    const float* bp   = (const float*)d_in[15];
    float* out = (float*)d_out;

    float *Qb, *Kb, *lg, *wb, *pq, *pk;
    __half *xqh, *xql, *xkh, *xkl, *Vh, *Vl, *Th, *Tl, *WT;
    cudaGetSymbolAddress((void**)&Qb, g_Q);
    cudaGetSymbolAddress((void**)&Kb, g_K);
    cudaGetSymbolAddress((void**)&lg, g_logits);
    cudaGetSymbolAddress((void**)&wb, g_wbuf);
    cudaGetSymbolAddress((void**)&pq, g_pq);
    cudaGetSymbolAddress((void**)&pk, g_pk);
    cudaGetSymbolAddress((void**)&xqh, g_xq_hi);
    cudaGetSymbolAddress((void**)&xql, g_xq_lo);
    cudaGetSymbolAddress((void**)&xkh, g_xkv_hi);
    cudaGetSymbolAddress((void**)&xkl, g_xkv_lo);
    cudaGetSymbolAddress((void**)&Vh, g_V_hi);
    cudaGetSymbolAddress((void**)&Vl, g_V_lo);
    cudaGetSymbolAddress((void**)&Th, g_T_hi);
    cudaGetSymbolAddress((void**)&Tl, g_T_lo);
    cudaGetSymbolAddress((void**)&WT, g_WT);

    const size_t WSZ = (size_t)Cdim * Cdim;
    __half *wq16 = WT + 0 * WSZ, *wk16 = WT + 1 * WSZ, *wv16 = WT + 2 * WSZ;
    __half *wt16 = WT + 3 * WSZ, *wp16 = WT + 4 * WSZ;

    cudaFuncSetAttribute(mma_gemm, cudaFuncAttributeMaxDynamicSharedMemorySize, SMEMB);

    int n4 = Mrows * Cdim / 4;
    dim3 wg(32, 32);
    // launches 0..4, so launch #5 (ncu -s 5 -c 1) is the first mma_gemm
    cvt_kernel<<<(n4 + 255) / 256, 256>>>(x_q, xqh, xql, n4);       // 0
    cvt_kernel<<<(n4 + 255) / 256, 256>>>(x_kv, xkh, xkl, n4);      // 1
    wcvt_kernel<<<wg, 256>>>(Wq, wq16);                             // 2
    wcvt_kernel<<<wg, 256>>>(Wk, wk16);                             // 3
    wcvt_kernel<<<wg, 256>>>(Wv, wv16);                             // 4

    dim3 gg(Cdim / 128, Mrows / 128);   // 8 x 256

    // 5: Q = x_q @ Wq + bq  (fp32)
    mma_gemm<<<gg, 256, SMEMB>>>(xqh, xql, wq16, bq, nullptr, nullptr,
                                 Qb, nullptr, nullptr);
    wcvt_kernel<<<wg, 256>>>(Wt, wt16);
    wcvt_kernel<<<wg, 256>>>(Wp, wp16);
    // q pooling
    attn_logits_kernel<<<Mrows / 8, 256>>>(Qb, Wqa, bqa, nullptr, lg);
    softmax_L_kernel<<<NB * Hn, 256>>>(lg, wb);
    pool_kernel<<<dim3(Hn, NB), 1024>>>(wb, Qb, pq);
    // K = x_kv @ Wk + bk  (fp32)
    mma_gemm<<<gg, 256, SMEMB>>>(xkh, xkl, wk16, bk, nullptr, nullptr,
                                 Kb, nullptr, nullptr);
    // k pooling (gated logits)
    attn_logits_kernel<<<Mrows / 8, 256>>>(Kb, Wka, bka, pq, lg);
    softmax_L_kernel<<<NB * Hn, 256>>>(lg, wb);
    pool_kernel<<<dim3(Hn, NB), 1024>>>(wb, Kb, pk);
    // Vs = (x_kv @ Wv + bv) * pk[n,col]  (fp16 hi/lo only)
    mma_gemm<<<gg, 256, SMEMB>>>(xkh, xkl, wv16, bv, pk, nullptr,
                                 nullptr, Vh, Vl);
    // T = Vs @ Wt + bt + Q  (fp16 hi/lo only)
    mma_gemm<<<gg, 256, SMEMB>>>(Vh, Vl, wt16, bt, nullptr, Qb,
                                 nullptr, Th, Tl);
    // out = T @ Wp + bp  (fp32)
    mma_gemm<<<gg, 256, SMEMB>>>(Th, Tl, wp16, bp, nullptr, nullptr,
                                 out, nullptr, nullptr);
}

// round 7
// speedup vs baseline: 10.0141x; 1.6530x over previous
#include <cuda_runtime.h>
#include <cuda_fp16.h>
#include <cstdint>

#define Cdim 1024
#define Hn   16
#define NB   8
#define Lseq 4096
#define Mrows (NB * Lseq)      // 32768
#define ATT_SCALE 0.125f

// ---------------------------------------------------------------------------
// Scratch
// ---------------------------------------------------------------------------
__device__ float g_Q[(size_t)Mrows * Cdim];
__device__ float g_K[(size_t)Mrows * Cdim];
__device__ float g_logits[(size_t)Mrows * Hn];
__device__ float g_wbuf[(size_t)NB * Hn * Lseq];
__device__ float g_pq[NB * Cdim];
__device__ float g_pk[NB * Cdim];

__device__ __half g_xq16[(size_t)Mrows * Cdim];
__device__ __half g_xkv16[(size_t)Mrows * Cdim];
__device__ __half g_V16[(size_t)Mrows * Cdim];
__device__ __half g_T16[(size_t)Mrows * Cdim];
__device__ __half g_WT[5][(size_t)Cdim * Cdim];

// ---------------------------------------------------------------------------
// PTX helpers
// ---------------------------------------------------------------------------
__device__ __forceinline__ uint32_t smem_u32(const void* p) {
    uint32_t a;
    asm("{ .reg .u64 t; cvta.to.shared.u64 t, %1; cvt.u32.u64 %0, t; }" : "=r"(a) : "l"(p));
    return a;
}
__device__ __forceinline__ void cpa16(uint32_t dst, const void* src) {
    asm volatile("cp.async.cg.shared.global [%0], [%1], 16;" :: "r"(dst), "l"(src) : "memory");
}
__device__ __forceinline__ void cpa_commit() {
    asm volatile("cp.async.commit_group;" ::: "memory");
}
__device__ __forceinline__ void cpa_wait1() {
    asm volatile("cp.async.wait_group 1;" ::: "memory");
}
__device__ __forceinline__ void ldm_x4(uint32_t* r, uint32_t addr) {
    asm volatile("ldmatrix.sync.aligned.m8n8.x4.shared.b16 {%0,%1,%2,%3}, [%4];"
                 : "=r"(r[0]), "=r"(r[1]), "=r"(r[2]), "=r"(r[3]) : "r"(addr));
}
__device__ __forceinline__ void mma_fp16(float* c, const uint32_t* a, const uint32_t* b) {
    asm volatile(
        "mma.sync.aligned.m16n8k16.row.col.f32.f16.f16.f32 "
        "{%0,%1,%2,%3}, {%4,%5,%6,%7}, {%8,%9}, {%0,%1,%2,%3};"
        : "+f"(c[0]), "+f"(c[1]), "+f"(c[2]), "+f"(c[3])
        : "r"(a[0]), "r"(a[1]), "r"(a[2]), "r"(a[3]), "r"(b[0]), "r"(b[1]));
}

// ---------------------------------------------------------------------------
// HMMA GEMM: out[M,1024] = A[M,1024] @ W[1024,1024] (+epilogues)
// A fp16 row-major; W fp16 K-major. Block 128x128, BK=64, 3 stages, 2 CTA/SM.
// ---------------------------------------------------------------------------
#define ROWB   144                 // 64 fp16 = 128B data + 16B pad
#define TILEB  (128 * ROWB)        // 18432
#define STAGEB (2 * TILEB)         // A, B -> 36864
#define STAGES 3
#define SMEMB  (STAGES * STAGEB)   // 110592

__device__ __forceinline__ void issue_stage(
    uint32_t sb, int s, int chunk, int tid,
    const __half* Aw, const __half* Bw, int grow0, int ncol0)
{
    uint32_t stb = sb + (uint32_t)s * STAGEB;
    int k0 = chunk * 64;
#pragma unroll
    for (int j = 0; j < 8; j++) {
        int id = tid + j * 256;            // 0..2047
        int t4 = id >> 10;                 // operand tile 0..1
        int w  = id & 1023;
        int r  = w >> 3, c = w & 7;        // row, 16B chunk
        const __half* src = (t4 == 0) ? Aw : Bw;
        int rb = (t4 == 0) ? grow0 : ncol0;
        const void* g = src + ((size_t)(rb + r) * Cdim + k0 + c * 8);
        cpa16(stb + (uint32_t)t4 * TILEB + (uint32_t)(r * ROWB + c * 16), g);
    }
}

__global__ void __launch_bounds__(256, 2) mma_gemm(
    const __half* __restrict__ Aw, const __half* __restrict__ Bw,
    const float* __restrict__ bias, const float* __restrict__ colscale,
    const float* __restrict__ addmat,
    float* __restrict__ outf, __half* __restrict__ out16)
{
    extern __shared__ char smem[];
    uint32_t sb = smem_u32(smem);
    int tid = threadIdx.x;
    int lane = tid & 31, wid = tid >> 5;
    int wm = wid & 1, wc = wid >> 1;           // warp 64x32 tile: 2 x 4 grid
    int bM = blockIdx.y * 128, bN = blockIdx.x * 128;

    float acc[4][4][4];
#pragma unroll
    for (int i = 0; i < 4; i++)
#pragma unroll
        for (int j = 0; j < 4; j++)
#pragma unroll
            for (int q = 0; q < 4; q++) acc[i][j][q] = 0.f;

    int grp = lane >> 3, l7 = lane & 7;
    uint32_t a_off = (uint32_t)((l7 + ((grp & 1) << 3)) * ROWB + ((grp >> 1) << 4));
    uint32_t b_off = (uint32_t)((l7 + ((grp >> 1) << 3)) * ROWB + ((grp & 1) << 4));

    // prologue: 2 chunks
#pragma unroll
    for (int s = 0; s < 2; s++) {
        issue_stage(sb, s, s, tid, Aw, Bw, bM, bN);
        cpa_commit();
    }

    for (int k = 0; k < 16; k++) {
        cpa_wait1();
        __syncthreads();
        if (k + 2 < 16)
            issue_stage(sb, (k + 2) % 3, k + 2, tid, Aw, Bw, bM, bN);
        cpa_commit();

        uint32_t st = sb + (uint32_t)(k % 3) * STAGEB;
#pragma unroll
        for (int kk = 0; kk < 4; kk++) {
            uint32_t kb = (uint32_t)(kk * 32);
            uint32_t bh[8];
#pragma unroll
            for (int h = 0; h < 2; h++) {
                uint32_t nrow = (uint32_t)((wc * 32 + h * 16) * ROWB);
                ldm_x4(bh + h * 4, st + TILEB + nrow + b_off + kb);
            }
#pragma unroll
            for (int mt = 0; mt < 4; mt++) {
                uint32_t mrow = (uint32_t)((wm * 64 + mt * 16) * ROWB);
                uint32_t ah[4];
                ldm_x4(ah, st + mrow + a_off + kb);
#pragma unroll
                for (int nt = 0; nt < 4; nt++)
                    mma_fp16(acc[mt][nt], ah, &bh[nt * 2]);
            }
        }
    }

    // ---------------- epilogue ----------------
    int nidx = bM >> 12;
#pragma unroll
    for (int mt = 0; mt < 4; mt++) {
        int m0 = bM + wm * 64 + mt * 16 + (lane >> 2);
#pragma unroll
        for (int nt = 0; nt < 4; nt++) {
            int n = bN + wc * 32 + nt * 8 + (lane & 3) * 2;
            float b0 = bias[n], b1 = bias[n + 1];
            float v0 = acc[mt][nt][0] + b0, v1 = acc[mt][nt][1] + b1;
            float v2 = acc[mt][nt][2] + b0, v3 = acc[mt][nt][3] + b1;
            if (colscale) {
                float s0 = colscale[nidx * Cdim + n];
                float s1 = colscale[nidx * Cdim + n + 1];
                v0 *= s0; v1 *= s1; v2 *= s0; v3 *= s1;
            }
            size_t o0 = (size_t)m0 * Cdim + n;
            size_t o1 = (size_t)(m0 + 8) * Cdim + n;
            if (addmat) {
                float2 a0 = *(const float2*)(addmat + o0);
                float2 a1 = *(const float2*)(addmat + o1);
                v0 += a0.x; v1 += a0.y; v2 += a1.x; v3 += a1.y;
            }
            if (outf) {
                *(float2*)(outf + o0) = make_float2(v0, v1);
                *(float2*)(outf + o1) = make_float2(v2, v3);
            }
            if (out16) {
                *(__half2*)(out16 + o0) =
                    __halves2half2(__float2half(v0), __float2half(v1));
                *(__half2*)(out16 + o1) =
                    __halves2half2(__float2half(v2), __float2half(v3));
            }
        }
    }
}

// ---------------------------------------------------------------------------
// fp32 -> fp16 elementwise
// ---------------------------------------------------------------------------
__global__ __launch_bounds__(256) void cvt_kernel(
    const float* __restrict__ src, __half* __restrict__ dst, int n4)
{
    int i = blockIdx.x * 256 + threadIdx.x;
    if (i >= n4) return;
    float4 x = ((const float4*)src)[i];
    __half2 a = __halves2half2(__float2half(x.x), __float2half(x.y));
    __half2 b = __halves2half2(__float2half(x.z), __float2half(x.w));
    ((__half2*)dst)[2 * i] = a;
    ((__half2*)dst)[2 * i + 1] = b;
}

// ---------------------------------------------------------------------------
// W[k][n] fp32 -> WT[n][k] fp16 (transpose-convert)
// ---------------------------------------------------------------------------
__global__ __launch_bounds__(256) void wcvt_kernel(
    const float* __restrict__ W, __half* __restrict__ T16)
{
    __shared__ float t[32][33];
    int tx = threadIdx.x & 31, ty = threadIdx.x >> 5;
    int n0 = blockIdx.x * 32, k0 = blockIdx.y * 32;
#pragma unroll
    for (int i = 0; i < 32; i += 8)
        t[ty + i][tx] = W[(size_t)(k0 + ty + i) * Cdim + n0 + tx];
    __syncthreads();
#pragma unroll
    for (int i = 0; i < 32; i += 8) {
        size_t o = (size_t)(n0 + ty + i) * Cdim + k0 + tx;
        T16[o] = __float2half(t[tx][ty + i]);
    }
}

// ---------------------------------------------------------------------------
// attention logits / softmax / pool
// ---------------------------------------------------------------------------
__global__ __launch_bounds__(256) void attn_logits_kernel(
    const float* __restrict__ A, const float* __restrict__ W16,
    const float* __restrict__ b16, const float* __restrict__ scalevec,
    float* __restrict__ logits)
{
    int warp = threadIdx.x >> 5, lane = threadIdx.x & 31;
    int row = blockIdx.x * 8 + warp;
    int n = row >> 12;
    const float* arow = A + (size_t)row * Cdim;
    const float* sv = scalevec ? scalevec + (size_t)n * Cdim : nullptr;

    float acc[16];
#pragma unroll
    for (int h = 0; h < 16; h++) acc[h] = 0.f;

    for (int c = lane; c < Cdim; c += 32) {
        float a = arow[c];
        if (sv) a *= sv[c];
        const float4* w4 = (const float4*)(W16 + (size_t)c * 16);
        float4 w0 = w4[0], w1 = w4[1], w2 = w4[2], w3 = w4[3];
        acc[0]  = fmaf(a, w0.x, acc[0]);  acc[1]  = fmaf(a, w0.y, acc[1]);
        acc[2]  = fmaf(a, w0.z, acc[2]);  acc[3]  = fmaf(a, w0.w, acc[3]);
        acc[4]  = fmaf(a, w1.x, acc[4]);  acc[5]  = fmaf(a, w1.y, acc[5]);
        acc[6]  = fmaf(a, w1.z, acc[6]);  acc[7]  = fmaf(a, w1.w, acc[7]);
        acc[8]  = fmaf(a, w2.x, acc[8]);  acc[9]  = fmaf(a, w2.y, acc[9]);
        acc[10] = fmaf(a, w2.z, acc[10]); acc[11] = fmaf(a, w2.w, acc[11]);
        acc[12] = fmaf(a, w3.x, acc[12]); acc[13] = fmaf(a, w3.y, acc[13]);
        acc[14] = fmaf(a, w3.z, acc[14]); acc[15] = fmaf(a, w3.w, acc[15]);
    }
#pragma unroll
    for (int h = 0; h < 16; h++) {
        float v = acc[h];
#pragma unroll
        for (int o = 16; o; o >>= 1) v += __shfl_xor_sync(0xffffffffu, v, o);
        if (lane == h) logits[(size_t)row * 16 + h] = (v + b16[h]) * ATT_SCALE;
    }
}

__global__ __launch_bounds__(256) void softmax_L_kernel(
    const float* __restrict__ logits, float* __restrict__ w_out)
{
    int n = blockIdx.x / Hn, h = blockIdx.x % Hn;
    __shared__ float buf[Lseq];
    __shared__ float red[256];
    int tid = threadIdx.x;

    float m = -1e30f;
    for (int l = tid; l < Lseq; l += 256) {
        float v = logits[((size_t)n * Lseq + l) * Hn + h];
        buf[l] = v;
        m = fmaxf(m, v);
    }
    red[tid] = m; __syncthreads();
    for (int s = 128; s; s >>= 1) {
        if (tid < s) red[tid] = fmaxf(red[tid], red[tid + s]);
        __syncthreads();
    }
    m = red[0]; __syncthreads();

    float sum = 0.f;
    for (int l = tid; l < Lseq; l += 256) {
        float e = __expf(buf[l] - m);
        buf[l] = e;
        sum += e;
    }
    red[tid] = sum; __syncthreads();
    for (int s = 128; s; s >>= 1) {
        if (tid < s) red[tid] += red[tid + s];
        __syncthreads();
    }
    float inv = 1.f / red[0];

    float* wp = w_out + ((size_t)n * Hn + h) * Lseq;
    for (int l = tid; l < Lseq; l += 256) wp[l] = buf[l] * inv;
}

__global__ __launch_bounds__(1024) void pool_kernel(
    const float* __restrict__ w, const float* __restrict__ A,
    float* __restrict__ pooled)
{
    int h = blockIdx.x, n = blockIdx.y;
    int tid = threadIdx.x;
    int dh = tid & 63, g = tid >> 6;

    const float* wp = w + ((size_t)n * Hn + h) * Lseq + g * 256;
    const float* ap = A + ((size_t)(n * Lseq + g * 256)) * Cdim + h * 64 + dh;

    float a0 = 0.f, a1 = 0.f, a2 = 0.f, a3 = 0.f;
    for (int l = 0; l < 256; l += 4) {
        a0 = fmaf(wp[l + 0], ap[(size_t)(l + 0) * Cdim], a0);
        a1 = fmaf(wp[l + 1], ap[(size_t)(l + 1) * Cdim], a1);
        a2 = fmaf(wp[l + 2], ap[(size_t)(l + 2) * Cdim], a2);
        a3 = fmaf(wp[l + 3], ap[(size_t)(l + 3) * Cdim], a3);
    }
    __shared__ float red[1024];
    red[tid] = a0 + a1 + a2 + a3;
    __syncthreads();
    if (tid < 64) {
        float s = 0.f;
#pragma unroll
        for (int gg = 0; gg < 16; gg++) s += red[dh + gg * 64];
        pooled[(size_t)n * Cdim + h * 64 + dh] = s;
    }
}

// ---------------------------------------------------------------------------
// Launch
// ---------------------------------------------------------------------------
extern "C" void kernel_launch(void* const* d_in, const int* in_sizes, int n_in,
                              void* d_out, int out_size)
{
    const float* x_q  = (const float*)d_in[0];
    const float* x_kv = (const float*)d_in[1];
    const float* Wq   = (const float*)d_in[2];
    const float* bq   = (const float*)d_in[3];
    const float* Wqa  = (const float*)d_in[4];
    const float* bqa  = (const float*)d_in[5];
    const float* Wk   = (const float*)d_in[6];
    const float* bk   = (const float*)d_in[7];
    const float* Wka  = (const float*)d_in[8];
    const float* bka  = (const float*)d_in[9];
    const float* Wv   = (const float*)d_in[10];
    const float* bv   = (const float*)d_in[11];
    const float* Wt   = (const float*)d_in[12];
    const float* bt   = (const float*)d_in[13];
    const float* Wp   = (const float*)d_in[14];
    const float* bp   = (const float*)d_in[15];
    float* out = (float*)d_out;

    float *Qb, *Kb, *lg, *wb, *pq, *pk;
    __half *xq16, *xkv16, *V16, *T16, *WT;
    cudaGetSymbolAddress((void**)&Qb, g_Q);
    cudaGetSymbolAddress((void**)&Kb, g_K);
    cudaGetSymbolAddress((void**)&lg, g_logits);
    cudaGetSymbolAddress((void**)&wb, g_wbuf);
    cudaGetSymbolAddress((void**)&pq, g_pq);
    cudaGetSymbolAddress((void**)&pk, g_pk);
    cudaGetSymbolAddress((void**)&xq16, g_xq16);
    cudaGetSymbolAddress((void**)&xkv16, g_xkv16);
    cudaGetSymbolAddress((void**)&V16, g_V16);
    cudaGetSymbolAddress((void**)&T16, g_T16);
    cudaGetSymbolAddress((void**)&WT, g_WT);

    const size_t WSZ = (size_t)Cdim * Cdim;
    __half *wq16 = WT + 0 * WSZ, *wk16 = WT + 1 * WSZ, *wv16 = WT + 2 * WSZ;
    __half *wt16 = WT + 3 * WSZ, *wp16 = WT + 4 * WSZ;

    cudaFuncSetAttribute(mma_gemm, cudaFuncAttributeMaxDynamicSharedMemorySize, SMEMB);

    int n4 = Mrows * Cdim / 4;
    dim3 wg(32, 32);
    cvt_kernel<<<(n4 + 255) / 256, 256>>>(x_q, xq16, n4);        // 0
    cvt_kernel<<<(n4 + 255) / 256, 256>>>(x_kv, xkv16, n4);      // 1
    wcvt_kernel<<<wg, 256>>>(Wq, wq16);                          // 2
    wcvt_kernel<<<wg, 256>>>(Wk, wk16);                          // 3
    wcvt_kernel<<<wg, 256>>>(Wv, wv16);                          // 4

    dim3 gg(Cdim / 128, Mrows / 128);   // 8 x 256

    // 5: Q = x_q @ Wq + bq  (fp32)
    mma_gemm<<<gg, 256, SMEMB>>>(xq16, wq16, bq, nullptr, nullptr, Qb, nullptr);
    wcvt_kernel<<<wg, 256>>>(Wt, wt16);
    wcvt_kernel<<<wg, 256>>>(Wp, wp16);
    // q pooling
    attn_logits_kernel<<<Mrows / 8, 256>>>(Qb, Wqa, bqa, nullptr, lg);
    softmax_L_kernel<<<NB * Hn, 256>>>(lg, wb);
    pool_kernel<<<dim3(Hn, NB), 1024>>>(wb, Qb, pq);
    // K = x_kv @ Wk + bk  (fp32)
    mma_gemm<<<gg, 256, SMEMB>>>(xkv16, wk16, bk, nullptr, nullptr, Kb, nullptr);
    // k pooling (gated logits)
    attn_logits_kernel<<<Mrows / 8, 256>>>(Kb, Wka, bka, pq, lg);
    softmax_L_kernel<<<NB * Hn, 256>>>(lg, wb);
    pool_kernel<<<dim3(Hn, NB), 1024>>>(wb, Kb, pk);
    // Vs = (x_kv @ Wv + bv) * pk[n,col]  (fp16 only)
    mma_gemm<<<gg, 256, SMEMB>>>(xkv16, wv16, bv, pk, nullptr, nullptr, V16);
    // T = Vs @ Wt + bt + Q  (fp16 only)
    mma_gemm<<<gg, 256, SMEMB>>>(V16, wt16, bt, nullptr, Qb, nullptr, T16);
    // out = T @ Wp + bp  (fp32)
    mma_gemm<<<gg, 256, SMEMB>>>(T16, wp16, bp, nullptr, nullptr, out, nullptr);
}